// round 5
// baseline (speedup 1.0000x reference)
#include <cuda_runtime.h>
#include <math.h>

#define N_NODES 100000
#define E_EDGES 1600000
#define V_IN    256
#define H_DIM   128
#define BN_EPS  1e-5f

// ---------------- scratch (static device globals; no allocs allowed) ----------------
__device__ float g_deg[N_NODES];                       // deg -> dinv (in place)
__device__ float g_norm[E_EDGES];                      // per-edge norm
__device__ float g_bufA[(size_t)N_NODES * 256];        // GEMM1 out: [xw1 | res], stride 256
__device__ float g_bufB[(size_t)N_NODES * H_DIM];      // out1 -> h1 (in place)
__device__ float g_bufC[(size_t)N_NODES * H_DIM];      // hw2
__device__ float g_bufD[(size_t)N_NODES * H_DIM];      // out2
__device__ float g_s[N_NODES];                         // h2 @ W3
__device__ float g_wcat[256 * 256];                    // [W1 | Wres] fused weights

// ---------------- small kernels ----------------
__global__ void deg_init_kernel(float* deg, int n) {
    int i = blockIdx.x * blockDim.x + threadIdx.x;
    if (i < n) deg[i] = 1.0f;   // self-loop weight
}

// edge_index is int32 (JAX silently downcasts int64 -> int32 without x64 mode)
__global__ void deg_acc_kernel(const int* __restrict__ ei,
                               const float* __restrict__ ew, float* deg, int e) {
    int idx = blockIdx.x * blockDim.x + threadIdx.x;
    if (idx < e) atomicAdd(&deg[ei[e + idx]], ew[idx]);
}

__global__ void deg_fin_kernel(float* deg, int n) {
    int i = blockIdx.x * blockDim.x + threadIdx.x;
    if (i < n) deg[i] = rsqrtf(deg[i]);   // deg >= 1 always (self loop)
}

__global__ void norm_kernel(const int* __restrict__ ei,
                            const float* __restrict__ ew,
                            const float* __restrict__ dinv,
                            float* __restrict__ nrm, int e) {
    int idx = blockIdx.x * blockDim.x + threadIdx.x;
    if (idx < e) {
        int r = ei[idx];
        int c = ei[e + idx];
        nrm[idx] = dinv[r] * ew[idx] * dinv[c];
    }
}

__global__ void build_wcat_kernel(const float* __restrict__ W1,
                                  const float* __restrict__ Wres,
                                  float* __restrict__ wcat) {
    int idx = blockIdx.x * blockDim.x + threadIdx.x;   // 65536
    int k = idx >> 8, nn = idx & 255;
    wcat[idx] = (nn < 128) ? W1[k * 128 + nn] : Wres[k * 128 + (nn - 128)];
}

// ---------------- SGEMM: C[M,N] = A[M,K] @ B[K,N], row-major, fp32 ----------------
#define GBM 128
#define GBN 128
#define GBK 8
#define GTM 8
#define GTN 8

__global__ __launch_bounds__(256) void sgemm_kernel(
    const float* __restrict__ A, const float* __restrict__ B,
    float* __restrict__ C, int M, int N, int K) {
    __shared__ float As[GBK][GBM];
    __shared__ float Bs[GBK][GBN];
    int tid = threadIdx.x;
    int tx = tid & 15;          // N dir (16)
    int ty = tid >> 4;          // M dir (16)
    int aRow = tid >> 1;               // 0..127
    int aCol = (tid & 1) * 4;          // 0 or 4
    int bRow = tid >> 5;               // 0..7
    int bCol = (tid & 31) * 4;         // 0..124
    int aGRow = blockIdx.y * GBM + aRow;
    if (aGRow >= M) aGRow = M - 1;     // clamp: tail block reads valid rows
    const float* Aptr = A + (size_t)aGRow * K + aCol;
    const float* Bptr = B + (size_t)bRow * N + blockIdx.x * GBN + bCol;

    float acc[GTM][GTN];
    #pragma unroll
    for (int i = 0; i < GTM; i++)
        #pragma unroll
        for (int j = 0; j < GTN; j++) acc[i][j] = 0.f;

    for (int k0 = 0; k0 < K; k0 += GBK) {
        float4 a = *(const float4*)(Aptr + k0);
        As[aCol + 0][aRow] = a.x;
        As[aCol + 1][aRow] = a.y;
        As[aCol + 2][aRow] = a.z;
        As[aCol + 3][aRow] = a.w;
        *(float4*)&Bs[bRow][bCol] = *(const float4*)(Bptr + (size_t)k0 * N);
        __syncthreads();
        #pragma unroll
        for (int k = 0; k < GBK; k++) {
            float ra[GTM], rb[GTN];
            #pragma unroll
            for (int i = 0; i < GTM; i++) ra[i] = As[k][ty * GTM + i];
            #pragma unroll
            for (int j = 0; j < GTN; j++) rb[j] = Bs[k][tx * GTN + j];
            #pragma unroll
            for (int i = 0; i < GTM; i++)
                #pragma unroll
                for (int j = 0; j < GTN; j++) acc[i][j] += ra[i] * rb[j];
        }
        __syncthreads();
    }
    #pragma unroll
    for (int i = 0; i < GTM; i++) {
        int r = blockIdx.y * GBM + ty * GTM + i;
        if (r < M) {
            float4* crow = (float4*)(C + (size_t)r * N + blockIdx.x * GBN + tx * GTN);
            crow[0] = make_float4(acc[i][0], acc[i][1], acc[i][2], acc[i][3]);
            crow[1] = make_float4(acc[i][4], acc[i][5], acc[i][6], acc[i][7]);
        }
    }
}

// ---------------- self-loop init: dst[i,:] = src[i,:] * dinv[i]^2 ----------------
__global__ void self_init_kernel(const float* __restrict__ src, int stride,
                                 const float* __restrict__ dinv,
                                 float* __restrict__ dst, int n) {
    int idx = blockIdx.x * blockDim.x + threadIdx.x;   // n*32 float4s
    if (idx >= n * 32) return;
    int i = idx >> 5, f4 = (idx & 31) * 4;
    float sn = dinv[i]; sn *= sn;
    float4 v = *(const float4*)(src + (size_t)i * stride + f4);
    v.x *= sn; v.y *= sn; v.z *= sn; v.w *= sn;
    *(float4*)(dst + (size_t)i * H_DIM + f4) = v;
}

// ---------------- edge scatter (128-wide): one warp per edge ----------------
__global__ __launch_bounds__(256) void scatter_feat_kernel(
    const int* __restrict__ ei, const float* __restrict__ nrm,
    const float* __restrict__ src, int srcStride,
    float* __restrict__ dst, int e) {
    int warp = (blockIdx.x * blockDim.x + threadIdx.x) >> 5;
    int lane = threadIdx.x & 31;
    if (warp >= e) return;
    int r = ei[warp];
    int c = ei[e + warp];
    float nv = nrm[warp];
    float4 v = *(const float4*)(src + (size_t)r * srcStride + lane * 4);
    float* d = dst + (size_t)c * H_DIM + lane * 4;
    asm volatile("red.global.add.v2.f32 [%0], {%1,%2};" ::
                 "l"(d), "f"(v.x * nv), "f"(v.y * nv) : "memory");
    asm volatile("red.global.add.v2.f32 [%0], {%1,%2};" ::
                 "l"(d + 2), "f"(v.z * nv), "f"(v.w * nv) : "memory");
}

// ---------------- BN1 + ReLU (in place): buf = relu(BN(buf + b1)) ----------------
__global__ void bn_relu_kernel(float* __restrict__ buf, const float* __restrict__ b,
                               const float* __restrict__ g, const float* __restrict__ be,
                               const float* __restrict__ m, const float* __restrict__ v,
                               int n) {
    int idx = blockIdx.x * blockDim.x + threadIdx.x;   // n*32 float4s
    if (idx >= n * 32) return;
    int f0 = (idx & 31) * 4;
    float4 val = *(float4*)(buf + (size_t)idx * 4);
    float* pv = &val.x;
    #pragma unroll
    for (int j = 0; j < 4; j++) {
        int f = f0 + j;
        float sc = g[f] * rsqrtf(v[f] + BN_EPS);
        float t = (pv[j] + b[f] - m[f]) * sc + be[f];
        pv[j] = fmaxf(t, 0.f);
    }
    *(float4*)(buf + (size_t)idx * 4) = val;
}

// ------ layer-2 epilogue: s[i] = relu(BN2(out2 + b2 + res)) . W3  (warp per row) ------
__global__ __launch_bounds__(256) void epi2_kernel(
    const float* __restrict__ out2, const float* __restrict__ bufA,
    const float* __restrict__ b2, const float* __restrict__ g2,
    const float* __restrict__ be2, const float* __restrict__ m2,
    const float* __restrict__ v2, const float* __restrict__ W3,
    float* __restrict__ s, int n) {
    int wid = (blockIdx.x * blockDim.x + threadIdx.x) >> 5;
    int lane = threadIdx.x & 31;
    if (wid >= n) return;
    int f0 = lane * 4;
    float4 o = *(const float4*)(out2 + (size_t)wid * H_DIM + f0);
    float4 r = *(const float4*)(bufA + (size_t)wid * 256 + 128 + f0);
    const float* po = &o.x; const float* pr = &r.x;
    float acc = 0.f;
    #pragma unroll
    for (int j = 0; j < 4; j++) {
        int f = f0 + j;
        float sc = g2[f] * rsqrtf(v2[f] + BN_EPS);
        float t = (po[j] + pr[j] + b2[f] - m2[f]) * sc + be2[f];
        acc += fmaxf(t, 0.f) * W3[f];
    }
    #pragma unroll
    for (int off = 16; off; off >>= 1)
        acc += __shfl_down_sync(0xffffffffu, acc, off);
    if (lane == 0) s[wid] = acc;
}

// ---------------- layer 3 (scalar) ----------------
__global__ void out_init_kernel(const float* __restrict__ s,
                                const float* __restrict__ dinv,
                                const float* __restrict__ b3,
                                float* __restrict__ out, int n) {
    int i = blockIdx.x * blockDim.x + threadIdx.x;
    if (i < n) {
        float d = dinv[i];
        out[i] = s[i] * d * d + b3[0];
    }
}

__global__ void scatter_scalar_kernel(const int* __restrict__ ei,
                                      const float* __restrict__ nrm,
                                      const float* __restrict__ s,
                                      float* __restrict__ out, int e) {
    int idx = blockIdx.x * blockDim.x + threadIdx.x;
    if (idx < e) {
        int r = ei[idx];
        int c = ei[e + idx];
        atomicAdd(&out[c], s[r] * nrm[idx]);
    }
}

// ---------------- launch ----------------
extern "C" void kernel_launch(void* const* d_in, const int* in_sizes, int n_in,
                              void* d_out, int out_size) {
    const float* x    = (const float*)d_in[0];
    const int*   ei   = (const int*)d_in[1];     // int32! (jax downcasts int64)
    const float* ew   = (const float*)d_in[2];
    const float* W1   = (const float*)d_in[3];
    const float* b1   = (const float*)d_in[4];
    const float* W2   = (const float*)d_in[5];
    const float* b2   = (const float*)d_in[6];
    const float* W3   = (const float*)d_in[7];
    const float* b3   = (const float*)d_in[8];
    const float* Wres = (const float*)d_in[9];
    const float* g1   = (const float*)d_in[10];
    const float* be1  = (const float*)d_in[11];
    const float* m1   = (const float*)d_in[12];
    const float* v1   = (const float*)d_in[13];
    const float* g2   = (const float*)d_in[14];
    const float* be2  = (const float*)d_in[15];
    const float* m2   = (const float*)d_in[16];
    const float* v2   = (const float*)d_in[17];
    float* out = (float*)d_out;

    int n = in_sizes[0] / V_IN;   // 100000
    int e = in_sizes[2];          // 1600000

    float *deg, *nrm, *bufA, *bufB, *bufC, *bufD, *s, *wcat;
    cudaGetSymbolAddress((void**)&deg,  g_deg);
    cudaGetSymbolAddress((void**)&nrm,  g_norm);
    cudaGetSymbolAddress((void**)&bufA, g_bufA);
    cudaGetSymbolAddress((void**)&bufB, g_bufB);
    cudaGetSymbolAddress((void**)&bufC, g_bufC);
    cudaGetSymbolAddress((void**)&bufD, g_bufD);
    cudaGetSymbolAddress((void**)&s,    g_s);
    cudaGetSymbolAddress((void**)&wcat, g_wcat);

    int nb_n   = (n + 255) / 256;
    int nb_e   = (e + 255) / 256;
    int nb_nf4 = (n * 32 + 255) / 256;        // n*128 floats as float4
    int nb_ew  = (e + 7) / 8;                 // warp per edge, 8 warps/block
    int nb_nw  = (n + 7) / 8;                 // warp per row

    // norm precompute
    deg_init_kernel<<<nb_n, 256>>>(deg, n);
    deg_acc_kernel<<<nb_e, 256>>>(ei, ew, deg, e);
    deg_fin_kernel<<<nb_n, 256>>>(deg, n);           // deg -> dinv in place
    norm_kernel<<<nb_e, 256>>>(ei, ew, deg, nrm, e);

    // fused GEMM1: bufA = x @ [W1 | Wres]   -> [n, 256]
    build_wcat_kernel<<<256, 256>>>(W1, Wres, wcat);
    {
        dim3 grid(256 / GBN, (n + GBM - 1) / GBM);
        sgemm_kernel<<<grid, 256>>>(x, wcat, bufA, n, 256, V_IN);
    }

    // layer 1 aggregation: bufB = A_hat @ xw1
    self_init_kernel<<<nb_nf4, 256>>>(bufA, 256, deg, bufB, n);
    scatter_feat_kernel<<<nb_ew, 256>>>(ei, nrm, bufA, 256, bufB, e);
    bn_relu_kernel<<<nb_nf4, 256>>>(bufB, b1, g1, be1, m1, v1, n);   // h1 in place

    // GEMM2: bufC = h1 @ W2
    {
        dim3 grid(1, (n + GBM - 1) / GBM);
        sgemm_kernel<<<grid, 256>>>(bufB, W2, bufC, n, H_DIM, H_DIM);
    }

    // layer 2 aggregation: bufD = A_hat @ hw2
    self_init_kernel<<<nb_nf4, 256>>>(bufC, H_DIM, deg, bufD, n);
    scatter_feat_kernel<<<nb_ew, 256>>>(ei, nrm, bufC, H_DIM, bufD, e);

    // epilogue: s = relu(BN2(bufD + b2 + res)) . W3
    epi2_kernel<<<nb_nw, 256>>>(bufD, bufA, b2, g2, be2, m2, v2, W3, s, n);

    // layer 3 (scalar aggregation) into d_out
    out_init_kernel<<<nb_n, 256>>>(s, deg, b3, out, n);
    scatter_scalar_kernel<<<nb_e, 256>>>(ei, nrm, s, out, e);
}

// round 7
// speedup vs baseline: 1.2326x; 1.2326x over previous
#include <cuda_runtime.h>
#include <math.h>
#include <stdint.h>

#define N_NODES 100000
#define E_EDGES 1600000
#define V_IN    256
#define H_DIM   128
#define BN_EPS  1e-5f

// ---------------- scratch (static device globals; no allocs allowed) ----------------
__device__ __align__(16) float g_deg[N_NODES];                 // deg -> dinv (in place)
__device__ __align__(16) float g_norm[E_EDGES];                // per-edge norm
__device__ __align__(16) float g_bufA[(size_t)N_NODES * 256];  // GEMM1 out: [xw1 | res], stride 256
__device__ __align__(16) float g_bufB[(size_t)N_NODES * H_DIM];// out1 (self-init, then aggregate)
__device__ __align__(16) float g_bufC[(size_t)N_NODES * H_DIM];// hw2
__device__ __align__(16) float g_bufD[(size_t)N_NODES * H_DIM];// out2
__device__ __align__(16) float g_s[N_NODES];                   // h2 @ W3
__device__ __align__(16) float g_B1hi[256 * 256];              // [W1|Wres] tf32-hi, [K,N]
__device__ __align__(16) float g_B1lo[256 * 256];              // tf32-lo
__device__ __align__(16) float g_B2hi[128 * 128];              // W2 hi, [K,N]
__device__ __align__(16) float g_B2lo[128 * 128];
__device__ __align__(16) float g_sc1[H_DIM];                   // BN1 scale
__device__ __align__(16) float g_sh1[H_DIM];                   // BN1 shift

// =================== tf32 helpers ===================
__device__ __forceinline__ float tf32r(float x) {
    float r; asm("cvt.rna.tf32.f32 %0, %1;" : "=f"(r) : "f"(x)); return r;
}
__device__ __forceinline__ void tf32_split(float x, uint32_t& h, uint32_t& l) {
    float hf = tf32r(x);
    float lf = tf32r(x - hf);
    h = __float_as_uint(hf);
    l = __float_as_uint(lf);
}
__device__ __forceinline__ void mma_tf32(float* d, const uint32_t* a,
                                         uint32_t b0, uint32_t b1) {
    asm volatile(
        "mma.sync.aligned.m16n8k8.row.col.f32.tf32.tf32.f32 "
        "{%0,%1,%2,%3}, {%4,%5,%6,%7}, {%8,%9}, {%0,%1,%2,%3};"
        : "+f"(d[0]), "+f"(d[1]), "+f"(d[2]), "+f"(d[3])
        : "r"(a[0]), "r"(a[1]), "r"(a[2]), "r"(a[3]), "r"(b0), "r"(b1));
}

// ---------------- small kernels ----------------
__global__ void deg_init_kernel(float* deg, int n) {
    int i = blockIdx.x * blockDim.x + threadIdx.x;
    if (i < n) deg[i] = 1.0f;
}
__global__ void deg_acc_kernel(const int* __restrict__ ei,
                               const float* __restrict__ ew, float* deg, int e) {
    int idx = blockIdx.x * blockDim.x + threadIdx.x;
    if (idx < e) atomicAdd(&deg[ei[e + idx]], ew[idx]);
}
__global__ void deg_fin_kernel(float* deg, int n) {
    int i = blockIdx.x * blockDim.x + threadIdx.x;
    if (i < n) deg[i] = rsqrtf(deg[i]);
}
__global__ void norm_kernel(const int* __restrict__ ei, const float* __restrict__ ew,
                            const float* __restrict__ dinv, float* __restrict__ nrm, int e) {
    int idx = blockIdx.x * blockDim.x + threadIdx.x;
    if (idx < e) nrm[idx] = dinv[ei[idx]] * ew[idx] * dinv[ei[e + idx]];
}

// weights -> tf32 hi/lo split, [K,N] layout (same as source; [W1|Wres] concatenated on N)
__global__ void split_B1_kernel(const float* __restrict__ W1, const float* __restrict__ Wres,
                                float* __restrict__ hi, float* __restrict__ lo) {
    int idx = blockIdx.x * blockDim.x + threadIdx.x;    // 65536; idx = k*256 + nn
    int k = idx >> 8, nn = idx & 255;
    float v = (nn < 128) ? W1[k * 128 + nn] : Wres[k * 128 + (nn - 128)];
    float h = tf32r(v);
    hi[idx] = h;
    lo[idx] = tf32r(v - h);
}
__global__ void split_B2_kernel(const float* __restrict__ W2,
                                float* __restrict__ hi, float* __restrict__ lo) {
    int idx = blockIdx.x * blockDim.x + threadIdx.x;    // 16384
    float v = W2[idx];
    float h = tf32r(v);
    hi[idx] = h;
    lo[idx] = tf32r(v - h);
}
__global__ void bn_pre_kernel(const float* b, const float* g, const float* be,
                              const float* m, const float* v,
                              float* sc, float* sh) {
    int f = threadIdx.x;
    float s = g[f] * rsqrtf(v[f] + BN_EPS);
    sc[f] = s;
    sh[f] = (b[f] - m[f]) * s + be[f];
}

// ====== tf32 3x-split MMA GEMM: C[M,Ntot] = A[M,K] @ B[K,Ntot] (B pre-split hi/lo) ======
// Fused: optional BN+ReLU on A load; optional self-loop init
//        selfDst[r, col] = C[r, col] * dinv[r]^2 for col < selfCols
// Block tile 128x128, 8 warps (4M x 2N), warp tile 32x64, BK=32.
#define ASTRIDE 36     // A smem row stride (floats): conflict-free frag loads
#define BSTRIDE 136    // B smem row stride
__global__ __launch_bounds__(256) void mma_gemm_kernel(
    const float* __restrict__ A, const float* __restrict__ Bhi, const float* __restrict__ Blo,
    float* __restrict__ C, int M, int Ntot, int K,
    const float* __restrict__ dinv, float* __restrict__ selfDst, int selfCols,
    const float* __restrict__ bnSc, const float* __restrict__ bnSh) {
    extern __shared__ uint32_t sm[];
    uint32_t* AsH = sm;                       // [128][36]
    uint32_t* AsL = sm + 128 * ASTRIDE;       // 4608
    uint32_t* BsH = sm + 2 * 128 * ASTRIDE;   // [32][136]
    uint32_t* BsL = BsH + 32 * BSTRIDE;

    const int tid = threadIdx.x;
    const int warpId = tid >> 5, lane = tid & 31;
    const int groupID = lane >> 2, tig = lane & 3;
    const int warpM = warpId & 3, warpN = warpId >> 2;
    const int m0 = blockIdx.y * 128;
    const int n0 = blockIdx.x * 128;

    float acc[2][8][4];
    #pragma unroll
    for (int i = 0; i < 2; i++)
        #pragma unroll
        for (int j = 0; j < 8; j++)
            #pragma unroll
            for (int q = 0; q < 4; q++) acc[i][j][q] = 0.f;

    const int nChunks = K >> 5;
    for (int c = 0; c < nChunks; c++) {
        // ---- A tile: 128 rows x 32 k, coalesced float4, BN+ReLU opt, split hi/lo ----
        #pragma unroll
        for (int t = 0; t < 4; t++) {
            int idx = tid + t * 256;          // 0..1023
            int row = idx >> 3;               // 0..127
            int cf = (idx & 7) * 4;           // 0,4,..28
            int gr = m0 + row; if (gr >= M) gr = M - 1;
            float4 v = *(const float4*)(A + (size_t)gr * K + c * 32 + cf);
            if (bnSc) {
                int f = c * 32 + cf;
                float4 sc4 = *(const float4*)(bnSc + f);
                float4 sh4 = *(const float4*)(bnSh + f);
                v.x = fmaxf(fmaf(v.x, sc4.x, sh4.x), 0.f);
                v.y = fmaxf(fmaf(v.y, sc4.y, sh4.y), 0.f);
                v.z = fmaxf(fmaf(v.z, sc4.z, sh4.z), 0.f);
                v.w = fmaxf(fmaf(v.w, sc4.w, sh4.w), 0.f);
            }
            uint4 h4, l4;
            tf32_split(v.x, h4.x, l4.x);
            tf32_split(v.y, h4.y, l4.y);
            tf32_split(v.z, h4.z, l4.z);
            tf32_split(v.w, h4.w, l4.w);
            *(uint4*)&AsH[row * ASTRIDE + cf] = h4;
            *(uint4*)&AsL[row * ASTRIDE + cf] = l4;
        }
        // ---- B tile: 32 k-rows x 128 cols, already split in gmem ----
        #pragma unroll
        for (int t = 0; t < 4; t++) {
            int idx = tid + t * 256;          // 0..1023
            int kk = idx >> 5;                // 0..31
            int nf = (idx & 31) * 4;          // 0..124
            size_t go = (size_t)(c * 32 + kk) * Ntot + n0 + nf;
            *(uint4*)&BsH[kk * BSTRIDE + nf] = *(const uint4*)(Bhi + go);
            *(uint4*)&BsL[kk * BSTRIDE + nf] = *(const uint4*)(Blo + go);
        }
        __syncthreads();

        #pragma unroll
        for (int ks = 0; ks < 4; ks++) {
            const int kb = ks * 8 + tig;
            uint32_t ah[2][4], al[2][4];
            #pragma unroll
            for (int mt = 0; mt < 2; mt++) {
                int mb = warpM * 32 + mt * 16 + groupID;
                ah[mt][0] = AsH[mb * ASTRIDE + kb];
                ah[mt][1] = AsH[(mb + 8) * ASTRIDE + kb];
                ah[mt][2] = AsH[mb * ASTRIDE + kb + 4];
                ah[mt][3] = AsH[(mb + 8) * ASTRIDE + kb + 4];
                al[mt][0] = AsL[mb * ASTRIDE + kb];
                al[mt][1] = AsL[(mb + 8) * ASTRIDE + kb];
                al[mt][2] = AsL[mb * ASTRIDE + kb + 4];
                al[mt][3] = AsL[(mb + 8) * ASTRIDE + kb + 4];
            }
            #pragma unroll
            for (int nt = 0; nt < 8; nt++) {
                int nb = warpN * 64 + nt * 8 + groupID;
                uint32_t bh0 = BsH[kb * BSTRIDE + nb];
                uint32_t bh1 = BsH[(kb + 4) * BSTRIDE + nb];
                uint32_t bl0 = BsL[kb * BSTRIDE + nb];
                uint32_t bl1 = BsL[(kb + 4) * BSTRIDE + nb];
                #pragma unroll
                for (int mt = 0; mt < 2; mt++) {
                    mma_tf32(acc[mt][nt], ah[mt], bh0, bh1);   // hi*hi
                    mma_tf32(acc[mt][nt], ah[mt], bl0, bl1);   // hi*lo
                    mma_tf32(acc[mt][nt], al[mt], bh0, bh1);   // lo*hi
                }
            }
        }
        __syncthreads();
    }

    // ---- epilogue: write C (+ optional self-loop init) ----
    #pragma unroll
    for (int mt = 0; mt < 2; mt++) {
        int row = m0 + warpM * 32 + mt * 16 + groupID;
        int row2 = row + 8;
        float d2a = 0.f, d2b = 0.f;
        if (selfDst) {
            if (row < M)  { float d = dinv[row];  d2a = d * d; }
            if (row2 < M) { float d = dinv[row2]; d2b = d * d; }
        }
        #pragma unroll
        for (int nt = 0; nt < 8; nt++) {
            int col = n0 + warpN * 64 + nt * 8 + tig * 2;
            if (row < M) {
                *(float2*)(C + (size_t)row * Ntot + col) =
                    make_float2(acc[mt][nt][0], acc[mt][nt][1]);
                if (selfDst && col < selfCols)
                    *(float2*)(selfDst + (size_t)row * selfCols + col) =
                        make_float2(acc[mt][nt][0] * d2a, acc[mt][nt][1] * d2a);
            }
            if (row2 < M) {
                *(float2*)(C + (size_t)row2 * Ntot + col) =
                    make_float2(acc[mt][nt][2], acc[mt][nt][3]);
                if (selfDst && col < selfCols)
                    *(float2*)(selfDst + (size_t)row2 * selfCols + col) =
                        make_float2(acc[mt][nt][2] * d2b, acc[mt][nt][3] * d2b);
            }
        }
    }
}

// ---------------- edge scatter (128-wide): one warp per edge ----------------
__global__ __launch_bounds__(256) void scatter_feat_kernel(
    const int* __restrict__ ei, const float* __restrict__ nrm,
    const float* __restrict__ src, int srcStride,
    float* __restrict__ dst, int e) {
    int warp = (blockIdx.x * blockDim.x + threadIdx.x) >> 5;
    int lane = threadIdx.x & 31;
    if (warp >= e) return;
    int r = ei[warp];
    int c = ei[e + warp];
    float nv = nrm[warp];
    float4 v = *(const float4*)(src + (size_t)r * srcStride + lane * 4);
    float* d = dst + (size_t)c * H_DIM + lane * 4;
    asm volatile("red.global.add.v2.f32 [%0], {%1,%2};" ::
                 "l"(d), "f"(v.x * nv), "f"(v.y * nv) : "memory");
    asm volatile("red.global.add.v2.f32 [%0], {%1,%2};" ::
                 "l"(d + 2), "f"(v.z * nv), "f"(v.w * nv) : "memory");
}

// ------ layer-2 epilogue: s[i] = relu(BN2(out2 + b2 + res)) . W3  (warp per row) ------
__global__ __launch_bounds__(256) void epi2_kernel(
    const float* __restrict__ out2, const float* __restrict__ bufA,
    const float* __restrict__ b2, const float* __restrict__ g2,
    const float* __restrict__ be2, const float* __restrict__ m2,
    const float* __restrict__ v2, const float* __restrict__ W3,
    float* __restrict__ s, int n) {
    int wid = (blockIdx.x * blockDim.x + threadIdx.x) >> 5;
    int lane = threadIdx.x & 31;
    if (wid >= n) return;
    int f0 = lane * 4;
    float4 o = *(const float4*)(out2 + (size_t)wid * H_DIM + f0);
    float4 r = *(const float4*)(bufA + (size_t)wid * 256 + 128 + f0);
    const float* po = &o.x; const float* pr = &r.x;
    float acc = 0.f;
    #pragma unroll
    for (int j = 0; j < 4; j++) {
        int f = f0 + j;
        float sc = g2[f] * rsqrtf(v2[f] + BN_EPS);
        float t = (po[j] + pr[j] + b2[f] - m2[f]) * sc + be2[f];
        acc += fmaxf(t, 0.f) * W3[f];
    }
    #pragma unroll
    for (int off = 16; off; off >>= 1)
        acc += __shfl_down_sync(0xffffffffu, acc, off);
    if (lane == 0) s[wid] = acc;
}

// ---------------- layer 3 (scalar) ----------------
__global__ void out_init_kernel(const float* __restrict__ s, const float* __restrict__ dinv,
                                const float* __restrict__ b3, float* __restrict__ out, int n) {
    int i = blockIdx.x * blockDim.x + threadIdx.x;
    if (i < n) { float d = dinv[i]; out[i] = s[i] * d * d + b3[0]; }
}
__global__ void scatter_scalar_kernel(const int* __restrict__ ei, const float* __restrict__ nrm,
                                      const float* __restrict__ s, float* __restrict__ out, int e) {
    int idx = blockIdx.x * blockDim.x + threadIdx.x;
    if (idx < e) atomicAdd(&out[ei[e + idx]], s[ei[idx]] * nrm[idx]);
}

// ---------------- launch ----------------
extern "C" void kernel_launch(void* const* d_in, const int* in_sizes, int n_in,
                              void* d_out, int out_size) {
    const float* x    = (const float*)d_in[0];
    const int*   ei   = (const int*)d_in[1];     // int32 (jax downcasts int64)
    const float* ew   = (const float*)d_in[2];
    const float* W1   = (const float*)d_in[3];
    const float* b1   = (const float*)d_in[4];
    const float* W2   = (const float*)d_in[5];
    const float* b2   = (const float*)d_in[6];
    const float* W3   = (const float*)d_in[7];
    const float* b3   = (const float*)d_in[8];
    const float* Wres = (const float*)d_in[9];
    const float* g1   = (const float*)d_in[10];
    const float* be1  = (const float*)d_in[11];
    const float* m1   = (const float*)d_in[12];
    const float* v1   = (const float*)d_in[13];
    const float* g2   = (const float*)d_in[14];
    const float* be2  = (const float*)d_in[15];
    const float* m2   = (const float*)d_in[16];
    const float* v2   = (const float*)d_in[17];
    float* out = (float*)d_out;

    int n = in_sizes[0] / V_IN;   // 100000
    int e = in_sizes[2];          // 1600000

    float *deg, *nrm, *bufA, *bufB, *bufC, *bufD, *s;
    float *B1hi, *B1lo, *B2hi, *B2lo, *sc1, *sh1;
    cudaGetSymbolAddress((void**)&deg,  g_deg);
    cudaGetSymbolAddress((void**)&nrm,  g_norm);
    cudaGetSymbolAddress((void**)&bufA, g_bufA);
    cudaGetSymbolAddress((void**)&bufB, g_bufB);
    cudaGetSymbolAddress((void**)&bufC, g_bufC);
    cudaGetSymbolAddress((void**)&bufD, g_bufD);
    cudaGetSymbolAddress((void**)&s,    g_s);
    cudaGetSymbolAddress((void**)&B1hi, g_B1hi);
    cudaGetSymbolAddress((void**)&B1lo, g_B1lo);
    cudaGetSymbolAddress((void**)&B2hi, g_B2hi);
    cudaGetSymbolAddress((void**)&B2lo, g_B2lo);
    cudaGetSymbolAddress((void**)&sc1,  g_sc1);
    cudaGetSymbolAddress((void**)&sh1,  g_sh1);

    int nb_n  = (n + 255) / 256;
    int nb_e  = (e + 255) / 256;
    int nb_ew = (e + 7) / 8;
    int nb_nw = (n + 7) / 8;
    int mTiles = (n + 127) / 128;

    // dyn smem: 2*128*36*4 (A hi/lo) + 2*32*136*4 (B hi/lo) = 36864 + 34816
    const int smemBytes = (2 * 128 * ASTRIDE + 2 * 32 * BSTRIDE) * 4;   // 71680
    static int attr_set = 0;
    if (!attr_set) {
        cudaFuncSetAttribute(mma_gemm_kernel,
                             cudaFuncAttributeMaxDynamicSharedMemorySize, smemBytes);
        attr_set = 1;
    }

    // norm precompute
    deg_init_kernel<<<nb_n, 256>>>(deg, n);
    deg_acc_kernel<<<nb_e, 256>>>(ei, ew, deg, e);
    deg_fin_kernel<<<nb_n, 256>>>(deg, n);
    norm_kernel<<<nb_e, 256>>>(ei, ew, deg, nrm, e);

    // weight tf32 split, BN1 scale/shift
    split_B1_kernel<<<256, 256>>>(W1, Wres, B1hi, B1lo);
    split_B2_kernel<<<64, 256>>>(W2, B2hi, B2lo);
    bn_pre_kernel<<<1, 128>>>(b1, g1, be1, m1, v1, sc1, sh1);

    // GEMM1: bufA = x @ [W1|Wres]; fused self-init bufB = bufA[:, :128] * dinv^2
    mma_gemm_kernel<<<dim3(2, mTiles), 256, smemBytes>>>(
        x, B1hi, B1lo, bufA, n, 256, 256, deg, bufB, H_DIM, nullptr, nullptr);

    // layer 1 aggregation into bufB (raw out1)
    scatter_feat_kernel<<<nb_ew, 256>>>(ei, nrm, bufA, 256, bufB, e);

    // GEMM2: bufC = relu(BN1(bufB)) @ W2 (BN+ReLU fused into A load);
    // fused self-init bufD = bufC * dinv^2
    mma_gemm_kernel<<<dim3(1, mTiles), 256, smemBytes>>>(
        bufB, B2hi, B2lo, bufC, n, 128, 128, deg, bufD, H_DIM, sc1, sh1);

    // layer 2 aggregation into bufD
    scatter_feat_kernel<<<nb_ew, 256>>>(ei, nrm, bufC, H_DIM, bufD, e);

    // epilogue: s = relu(BN2(bufD + b2 + res)) . W3
    epi2_kernel<<<nb_nw, 256>>>(bufD, bufA, b2, g2, be2, m2, v2, W3, s, n);

    // layer 3 (scalar aggregation) into d_out
    out_init_kernel<<<nb_n, 256>>>(s, deg, b3, out, n);
    scatter_scalar_kernel<<<nb_e, 256>>>(ei, nrm, s, out, e);
}

// round 8
// speedup vs baseline: 1.2561x; 1.0191x over previous
#include <cuda_runtime.h>
#include <math.h>
#include <stdint.h>

#define N_NODES 100000
#define E_EDGES 1600000
#define V_IN    256
#define H_DIM   128
#define BN_EPS  1e-5f

// ---------------- scratch (static device globals; no allocs allowed) ----------------
__device__ __align__(16) float g_deg[N_NODES];                 // deg -> dinv (in place)
__device__ __align__(16) float g_norm[E_EDGES];                // per-edge norm
__device__ __align__(16) float g_bufA[(size_t)N_NODES * 256];  // GEMM1 out: [xw1 | res], stride 256
__device__ __align__(16) float g_bufB[(size_t)N_NODES * H_DIM];// out1 (self-init, then aggregate)
__device__ __align__(16) float g_bufC[(size_t)N_NODES * H_DIM];// hw2
__device__ __align__(16) float g_bufD[(size_t)N_NODES * H_DIM];// out2
__device__ __align__(16) float g_s[N_NODES];                   // h2 @ W3
__device__ __align__(16) uint32_t g_B1hi[256 * 128];           // [W1|Wres] bf16-hi pairs [N][K/2]
__device__ __align__(16) uint32_t g_B1lo[256 * 128];
__device__ __align__(16) uint32_t g_B2hi[128 * 64];            // W2 pairs [N][K/2]
__device__ __align__(16) uint32_t g_B2lo[128 * 64];
__device__ __align__(16) float g_sc1[H_DIM];                   // BN1 scale
__device__ __align__(16) float g_sh1[H_DIM];                   // BN1 shift

// =================== bf16 split helpers ===================
// pack two floats into bf16x2: low half = x0, high half = x1 (k-even in low)
__device__ __forceinline__ uint32_t pack_bf16x2(float x1, float x0) {
    uint32_t r;
    asm("cvt.rn.bf16x2.f32 %0, %1, %2;" : "=r"(r) : "f"(x1), "f"(x0));
    return r;
}
__device__ __forceinline__ float bf16_lo_f(uint32_t h) { return __uint_as_float(h << 16); }
__device__ __forceinline__ float bf16_hi_f(uint32_t h) { return __uint_as_float(h & 0xFFFF0000u); }

__device__ __forceinline__ void split_pair(float x0, float x1, uint32_t& hi, uint32_t& lo) {
    hi = pack_bf16x2(x1, x0);
    lo = pack_bf16x2(x1 - bf16_hi_f(hi), x0 - bf16_lo_f(hi));
}

__device__ __forceinline__ void mma_bf16(float* d, const uint32_t* a,
                                         uint32_t b0, uint32_t b1) {
    asm volatile(
        "mma.sync.aligned.m16n8k16.row.col.f32.bf16.bf16.f32 "
        "{%0,%1,%2,%3}, {%4,%5,%6,%7}, {%8,%9}, {%0,%1,%2,%3};"
        : "+f"(d[0]), "+f"(d[1]), "+f"(d[2]), "+f"(d[3])
        : "r"(a[0]), "r"(a[1]), "r"(a[2]), "r"(a[3]), "r"(b0), "r"(b1));
}

// ---------------- small kernels ----------------
__global__ void deg_init_kernel(float* deg, int n) {
    int i = blockIdx.x * blockDim.x + threadIdx.x;
    if (i < n) deg[i] = 1.0f;
}
__global__ void deg_acc_kernel(const int* __restrict__ ei,
                               const float* __restrict__ ew, float* deg, int e) {
    int idx = blockIdx.x * blockDim.x + threadIdx.x;
    if (idx < e) atomicAdd(&deg[ei[e + idx]], ew[idx]);
}
__global__ void deg_fin_kernel(float* deg, int n) {
    int i = blockIdx.x * blockDim.x + threadIdx.x;
    if (i < n) deg[i] = rsqrtf(deg[i]);
}
__global__ void norm_kernel(const int* __restrict__ ei, const float* __restrict__ ew,
                            const float* __restrict__ dinv, float* __restrict__ nrm, int e) {
    int idx = blockIdx.x * blockDim.x + threadIdx.x;
    if (idx < e) nrm[idx] = dinv[ei[idx]] * ew[idx] * dinv[ei[e + idx]];
}

// weights -> bf16 hi/lo pairs, [N][K/2] layout (B^T, K-major, packed k-pairs)
__global__ void split_B1_kernel(const float* __restrict__ W1, const float* __restrict__ Wres,
                                uint32_t* __restrict__ hi, uint32_t* __restrict__ lo) {
    int idx = blockIdx.x * blockDim.x + threadIdx.x;    // 32768; idx = n*128 + p
    int nn = idx >> 7, p = idx & 127;
    float v0, v1;
    if (nn < 128) { v0 = W1[(2 * p) * 128 + nn];     v1 = W1[(2 * p + 1) * 128 + nn]; }
    else          { v0 = Wres[(2 * p) * 128 + nn - 128]; v1 = Wres[(2 * p + 1) * 128 + nn - 128]; }
    uint32_t h, l;
    split_pair(v0, v1, h, l);
    hi[idx] = h; lo[idx] = l;
}
__global__ void split_B2_kernel(const float* __restrict__ W2,
                                uint32_t* __restrict__ hi, uint32_t* __restrict__ lo) {
    int idx = blockIdx.x * blockDim.x + threadIdx.x;    // 8192; idx = n*64 + p
    int nn = idx >> 6, p = idx & 63;
    float v0 = W2[(2 * p) * 128 + nn];
    float v1 = W2[(2 * p + 1) * 128 + nn];
    uint32_t h, l;
    split_pair(v0, v1, h, l);
    hi[idx] = h; lo[idx] = l;
}
__global__ void bn_pre_kernel(const float* b, const float* g, const float* be,
                              const float* m, const float* v,
                              float* sc, float* sh) {
    int f = threadIdx.x;
    float s = g[f] * rsqrtf(v[f] + BN_EPS);
    sc[f] = s;
    sh[f] = (b[f] - m[f]) * s + be[f];
}

// ====== bf16 3x-split MMA GEMM: C[M,Ntot] = A[M,K] @ B (B pre-split [N][K/2] pairs) ======
// Fused: optional BN+ReLU on A load; optional self-loop init
//        selfDst[r, col] = C[r, col] * dinv[r]^2 for col < selfCols
// Block tile 128x128, 8 warps (4M x 2N), warp tile 32x64, BK=32 (2 x k16 steps).
#define PSTRIDE 20     // smem row stride in uint32 pairs: conflict-free frag loads
__global__ __launch_bounds__(256) void mma_gemm_kernel(
    const float* __restrict__ A,
    const uint32_t* __restrict__ Bhi, const uint32_t* __restrict__ Blo,
    float* __restrict__ C, int M, int Ntot, int K,
    const float* __restrict__ dinv, float* __restrict__ selfDst, int selfCols,
    const float* __restrict__ bnSc, const float* __restrict__ bnSh) {
    __shared__ uint32_t AsH[128 * PSTRIDE];
    __shared__ uint32_t AsL[128 * PSTRIDE];
    __shared__ uint32_t BsH[128 * PSTRIDE];
    __shared__ uint32_t BsL[128 * PSTRIDE];

    const int tid = threadIdx.x;
    const int warpId = tid >> 5, lane = tid & 31;
    const int groupID = lane >> 2, tig = lane & 3;
    const int warpM = warpId & 3, warpN = warpId >> 2;
    const int m0 = blockIdx.y * 128;
    const int n0 = blockIdx.x * 128;
    const int Kp = K >> 1;      // pairs per B row

    float acc[2][8][4];
    #pragma unroll
    for (int i = 0; i < 2; i++)
        #pragma unroll
        for (int j = 0; j < 8; j++)
            #pragma unroll
            for (int q = 0; q < 4; q++) acc[i][j][q] = 0.f;

    const int nChunks = K >> 5;
    for (int c = 0; c < nChunks; c++) {
        // ---- A tile: 128 rows x 32 k, coalesced float4, BN+ReLU opt, bf16 split ----
        #pragma unroll
        for (int t = 0; t < 4; t++) {
            int idx = tid + t * 256;          // 0..1023
            int row = idx >> 3;               // 0..127
            int cf = (idx & 7) * 4;           // k offset in chunk: 0,4,..28
            int gr = m0 + row; if (gr >= M) gr = M - 1;
            float4 v = *(const float4*)(A + (size_t)gr * K + c * 32 + cf);
            if (bnSc) {
                int f = c * 32 + cf;
                float4 sc4 = *(const float4*)(bnSc + f);
                float4 sh4 = *(const float4*)(bnSh + f);
                v.x = fmaxf(fmaf(v.x, sc4.x, sh4.x), 0.f);
                v.y = fmaxf(fmaf(v.y, sc4.y, sh4.y), 0.f);
                v.z = fmaxf(fmaf(v.z, sc4.z, sh4.z), 0.f);
                v.w = fmaxf(fmaf(v.w, sc4.w, sh4.w), 0.f);
            }
            uint2 h2, l2;
            split_pair(v.x, v.y, h2.x, l2.x);
            split_pair(v.z, v.w, h2.y, l2.y);
            int so = row * PSTRIDE + (cf >> 1);          // pair index, even -> uint2 ok
            *(uint2*)&AsH[so] = h2;
            *(uint2*)&AsL[so] = l2;
        }
        // ---- B tile: 128 n-rows x 16 pairs, pre-split in gmem ----
        #pragma unroll
        for (int t = 0; t < 2; t++) {
            int idx = tid + t * 256;          // 0..511
            int nn = idx >> 2;                // 0..127
            int q = (idx & 3) * 4;            // pair 0,4,8,12
            size_t go = (size_t)(n0 + nn) * Kp + c * 16 + q;
            int so = nn * PSTRIDE + q;
            *(uint4*)&BsH[so] = *(const uint4*)(Bhi + go);
            *(uint4*)&BsL[so] = *(const uint4*)(Blo + go);
        }
        __syncthreads();

        #pragma unroll
        for (int s = 0; s < 2; s++) {
            const int kp = s * 8 + tig;       // pair index of k-step
            uint32_t ah[2][4], al[2][4];
            #pragma unroll
            for (int mt = 0; mt < 2; mt++) {
                int mb = warpM * 32 + mt * 16 + groupID;
                ah[mt][0] = AsH[mb * PSTRIDE + kp];
                ah[mt][1] = AsH[(mb + 8) * PSTRIDE + kp];
                ah[mt][2] = AsH[mb * PSTRIDE + kp + 4];
                ah[mt][3] = AsH[(mb + 8) * PSTRIDE + kp + 4];
                al[mt][0] = AsL[mb * PSTRIDE + kp];
                al[mt][1] = AsL[(mb + 8) * PSTRIDE + kp];
                al[mt][2] = AsL[mb * PSTRIDE + kp + 4];
                al[mt][3] = AsL[(mb + 8) * PSTRIDE + kp + 4];
            }
            #pragma unroll
            for (int nt = 0; nt < 8; nt++) {
                int nb = warpN * 64 + nt * 8 + groupID;
                uint32_t bh0 = BsH[nb * PSTRIDE + kp];
                uint32_t bh1 = BsH[nb * PSTRIDE + kp + 4];
                uint32_t bl0 = BsL[nb * PSTRIDE + kp];
                uint32_t bl1 = BsL[nb * PSTRIDE + kp + 4];
                #pragma unroll
                for (int mt = 0; mt < 2; mt++) {
                    mma_bf16(acc[mt][nt], ah[mt], bh0, bh1);   // hi*hi
                    mma_bf16(acc[mt][nt], ah[mt], bl0, bl1);   // hi*lo
                    mma_bf16(acc[mt][nt], al[mt], bh0, bh1);   // lo*hi
                }
            }
        }
        __syncthreads();
    }

    // ---- epilogue: write C (+ optional self-loop init) ----
    #pragma unroll
    for (int mt = 0; mt < 2; mt++) {
        int row = m0 + warpM * 32 + mt * 16 + groupID;
        int row2 = row + 8;
        float d2a = 0.f, d2b = 0.f;
        if (selfDst) {
            if (row < M)  { float d = dinv[row];  d2a = d * d; }
            if (row2 < M) { float d = dinv[row2]; d2b = d * d; }
        }
        #pragma unroll
        for (int nt = 0; nt < 8; nt++) {
            int col = n0 + warpN * 64 + nt * 8 + tig * 2;
            if (row < M) {
                *(float2*)(C + (size_t)row * Ntot + col) =
                    make_float2(acc[mt][nt][0], acc[mt][nt][1]);
                if (selfDst && col < selfCols)
                    *(float2*)(selfDst + (size_t)row * selfCols + col) =
                        make_float2(acc[mt][nt][0] * d2a, acc[mt][nt][1] * d2a);
            }
            if (row2 < M) {
                *(float2*)(C + (size_t)row2 * Ntot + col) =
                    make_float2(acc[mt][nt][2], acc[mt][nt][3]);
                if (selfDst && col < selfCols)
                    *(float2*)(selfDst + (size_t)row2 * selfCols + col) =
                        make_float2(acc[mt][nt][2] * d2b, acc[mt][nt][3] * d2b);
            }
        }
    }
}

// ---------------- edge scatter (128-wide): one warp per edge ----------------
__global__ __launch_bounds__(256) void scatter_feat_kernel(
    const int* __restrict__ ei, const float* __restrict__ nrm,
    const float* __restrict__ src, int srcStride,
    float* __restrict__ dst, int e) {
    int warp = (blockIdx.x * blockDim.x + threadIdx.x) >> 5;
    int lane = threadIdx.x & 31;
    if (warp >= e) return;
    int r = ei[warp];
    int c = ei[e + warp];
    float nv = nrm[warp];
    float4 v = *(const float4*)(src + (size_t)r * srcStride + lane * 4);
    float* d = dst + (size_t)c * H_DIM + lane * 4;
    asm volatile("red.global.add.v2.f32 [%0], {%1,%2};" ::
                 "l"(d), "f"(v.x * nv), "f"(v.y * nv) : "memory");
    asm volatile("red.global.add.v2.f32 [%0], {%1,%2};" ::
                 "l"(d + 2), "f"(v.z * nv), "f"(v.w * nv) : "memory");
}

// ------ layer-2 epilogue: s[i] = relu(BN2(out2 + b2 + res)) . W3  (warp per row) ------
__global__ __launch_bounds__(256) void epi2_kernel(
    const float* __restrict__ out2, const float* __restrict__ bufA,
    const float* __restrict__ b2, const float* __restrict__ g2,
    const float* __restrict__ be2, const float* __restrict__ m2,
    const float* __restrict__ v2, const float* __restrict__ W3,
    float* __restrict__ s, int n) {
    int wid = (blockIdx.x * blockDim.x + threadIdx.x) >> 5;
    int lane = threadIdx.x & 31;
    if (wid >= n) return;
    int f0 = lane * 4;
    float4 o = *(const float4*)(out2 + (size_t)wid * H_DIM + f0);
    float4 r = *(const float4*)(bufA + (size_t)wid * 256 + 128 + f0);
    const float* po = &o.x; const float* pr = &r.x;
    float acc = 0.f;
    #pragma unroll
    for (int j = 0; j < 4; j++) {
        int f = f0 + j;
        float sc = g2[f] * rsqrtf(v2[f] + BN_EPS);
        float t = (po[j] + pr[j] + b2[f] - m2[f]) * sc + be2[f];
        acc += fmaxf(t, 0.f) * W3[f];
    }
    #pragma unroll
    for (int off = 16; off; off >>= 1)
        acc += __shfl_down_sync(0xffffffffu, acc, off);
    if (lane == 0) s[wid] = acc;
}

// ---------------- layer 3 (scalar) ----------------
__global__ void out_init_kernel(const float* __restrict__ s, const float* __restrict__ dinv,
                                const float* __restrict__ b3, float* __restrict__ out, int n) {
    int i = blockIdx.x * blockDim.x + threadIdx.x;
    if (i < n) { float d = dinv[i]; out[i] = s[i] * d * d + b3[0]; }
}
__global__ void scatter_scalar_kernel(const int* __restrict__ ei, const float* __restrict__ nrm,
                                      const float* __restrict__ s, float* __restrict__ out, int e) {
    int idx = blockIdx.x * blockDim.x + threadIdx.x;
    if (idx < e) atomicAdd(&out[ei[e + idx]], s[ei[idx]] * nrm[idx]);
}

// ---------------- launch ----------------
extern "C" void kernel_launch(void* const* d_in, const int* in_sizes, int n_in,
                              void* d_out, int out_size) {
    const float* x    = (const float*)d_in[0];
    const int*   ei   = (const int*)d_in[1];     // int32 (jax downcasts int64)
    const float* ew   = (const float*)d_in[2];
    const float* W1   = (const float*)d_in[3];
    const float* b1   = (const float*)d_in[4];
    const float* W2   = (const float*)d_in[5];
    const float* b2   = (const float*)d_in[6];
    const float* W3   = (const float*)d_in[7];
    const float* b3   = (const float*)d_in[8];
    const float* Wres = (const float*)d_in[9];
    const float* g1   = (const float*)d_in[10];
    const float* be1  = (const float*)d_in[11];
    const float* m1   = (const float*)d_in[12];
    const float* v1   = (const float*)d_in[13];
    const float* g2   = (const float*)d_in[14];
    const float* be2  = (const float*)d_in[15];
    const float* m2   = (const float*)d_in[16];
    const float* v2   = (const float*)d_in[17];
    float* out = (float*)d_out;

    int n = in_sizes[0] / V_IN;   // 100000
    int e = in_sizes[2];          // 1600000

    float *deg, *nrm, *bufA, *bufB, *bufC, *bufD, *s, *sc1, *sh1;
    uint32_t *B1hi, *B1lo, *B2hi, *B2lo;
    cudaGetSymbolAddress((void**)&deg,  g_deg);
    cudaGetSymbolAddress((void**)&nrm,  g_norm);
    cudaGetSymbolAddress((void**)&bufA, g_bufA);
    cudaGetSymbolAddress((void**)&bufB, g_bufB);
    cudaGetSymbolAddress((void**)&bufC, g_bufC);
    cudaGetSymbolAddress((void**)&bufD, g_bufD);
    cudaGetSymbolAddress((void**)&s,    g_s);
    cudaGetSymbolAddress((void**)&B1hi, g_B1hi);
    cudaGetSymbolAddress((void**)&B1lo, g_B1lo);
    cudaGetSymbolAddress((void**)&B2hi, g_B2hi);
    cudaGetSymbolAddress((void**)&B2lo, g_B2lo);
    cudaGetSymbolAddress((void**)&sc1,  g_sc1);
    cudaGetSymbolAddress((void**)&sh1,  g_sh1);

    int nb_n  = (n + 255) / 256;
    int nb_e  = (e + 255) / 256;
    int nb_ew = (e + 7) / 8;
    int nb_nw = (n + 7) / 8;
    int mTiles = (n + 127) / 128;

    // norm precompute
    deg_init_kernel<<<nb_n, 256>>>(deg, n);
    deg_acc_kernel<<<nb_e, 256>>>(ei, ew, deg, e);
    deg_fin_kernel<<<nb_n, 256>>>(deg, n);
    norm_kernel<<<nb_e, 256>>>(ei, ew, deg, nrm, e);

    // weight bf16 split (packed pairs), BN1 scale/shift
    split_B1_kernel<<<128, 256>>>(W1, Wres, B1hi, B1lo);
    split_B2_kernel<<<32, 256>>>(W2, B2hi, B2lo);
    bn_pre_kernel<<<1, 128>>>(b1, g1, be1, m1, v1, sc1, sh1);

    // GEMM1: bufA = x @ [W1|Wres]; fused self-init bufB = bufA[:, :128] * dinv^2
    mma_gemm_kernel<<<dim3(2, mTiles), 256>>>(
        x, B1hi, B1lo, bufA, n, 256, 256, deg, bufB, H_DIM, nullptr, nullptr);

    // layer 1 aggregation into bufB (raw out1)
    scatter_feat_kernel<<<nb_ew, 256>>>(ei, nrm, bufA, 256, bufB, e);

    // GEMM2: bufC = relu(BN1(bufB)) @ W2 (BN+ReLU fused into A load);
    // fused self-init bufD = bufC * dinv^2
    mma_gemm_kernel<<<dim3(1, mTiles), 256>>>(
        bufB, B2hi, B2lo, bufC, n, 128, 128, deg, bufD, H_DIM, sc1, sh1);

    // layer 2 aggregation into bufD
    scatter_feat_kernel<<<nb_ew, 256>>>(ei, nrm, bufC, H_DIM, bufD, e);

    // epilogue: s = relu(BN2(bufD + b2 + res)) . W3
    epi2_kernel<<<nb_nw, 256>>>(bufD, bufA, b2, g2, be2, m2, v2, W3, s, n);

    // layer 3 (scalar aggregation) into d_out
    out_init_kernel<<<nb_n, 256>>>(s, deg, b3, out, n);
    scatter_scalar_kernel<<<nb_e, 256>>>(ei, nrm, s, out, e);
}

// round 9
// speedup vs baseline: 2.2661x; 1.8040x over previous
#include <cuda_runtime.h>
#include <math.h>
#include <stdint.h>

#define N_NODES 100000
#define E_EDGES 1600000
#define V_IN    256
#define H_DIM   128
#define BN_EPS  1e-5f

// ---------------- scratch (static device globals; no allocs allowed) ----------------
__device__ __align__(16) float g_deg[N_NODES];                 // deg -> dinv (in place)
__device__ __align__(16) int   g_hist[N_NODES];                // in-degree histogram
__device__ __align__(16) int   g_rowptr[N_NODES + 1];          // CSR row pointers (by dst)
__device__ __align__(16) int   g_cursor[N_NODES];              // fill cursors
__device__ __align__(16) int   g_bsums[128];                   // scan block sums
__device__ __align__(16) int2  g_csr[E_EDGES];                 // {src, bitcast(u=dinv[src]*ew)}
__device__ __align__(16) float g_bufE[(size_t)N_NODES * H_DIM];// xW1 (contiguous)
__device__ __align__(16) float g_bufR[(size_t)N_NODES * H_DIM];// x Wres (residual)
__device__ __align__(16) float g_bufB[(size_t)N_NODES * H_DIM];// h1 = relu(BN1(out1))
__device__ __align__(16) float g_bufC[(size_t)N_NODES * H_DIM];// h1 @ W2
__device__ __align__(16) float g_s[N_NODES];                   // h2 @ W3
__device__ __align__(16) uint32_t g_B1hi[256 * 128];           // [W1|Wres] bf16-hi pairs [N][K/2]
__device__ __align__(16) uint32_t g_B1lo[256 * 128];
__device__ __align__(16) uint32_t g_B2hi[128 * 64];            // W2 pairs [N][K/2]
__device__ __align__(16) uint32_t g_B2lo[128 * 64];
__device__ __align__(16) float g_sc1[H_DIM];                   // BN1 scale (b1 folded)
__device__ __align__(16) float g_sh1[H_DIM];
__device__ __align__(16) float g_sc2[H_DIM];                   // BN2 scale (b2 folded)
__device__ __align__(16) float g_sh2[H_DIM];

// =================== bf16 split helpers ===================
__device__ __forceinline__ uint32_t pack_bf16x2(float x1, float x0) {
    uint32_t r;
    asm("cvt.rn.bf16x2.f32 %0, %1, %2;" : "=r"(r) : "f"(x1), "f"(x0));
    return r;
}
__device__ __forceinline__ float bf16_lo_f(uint32_t h) { return __uint_as_float(h << 16); }
__device__ __forceinline__ float bf16_hi_f(uint32_t h) { return __uint_as_float(h & 0xFFFF0000u); }
__device__ __forceinline__ void split_pair(float x0, float x1, uint32_t& hi, uint32_t& lo) {
    hi = pack_bf16x2(x1, x0);
    lo = pack_bf16x2(x1 - bf16_hi_f(hi), x0 - bf16_lo_f(hi));
}
__device__ __forceinline__ void mma_bf16(float* d, const uint32_t* a,
                                         uint32_t b0, uint32_t b1) {
    asm volatile(
        "mma.sync.aligned.m16n8k16.row.col.f32.bf16.bf16.f32 "
        "{%0,%1,%2,%3}, {%4,%5,%6,%7}, {%8,%9}, {%0,%1,%2,%3};"
        : "+f"(d[0]), "+f"(d[1]), "+f"(d[2]), "+f"(d[3])
        : "r"(a[0]), "r"(a[1]), "r"(a[2]), "r"(a[3]), "r"(b0), "r"(b1));
}

// ---------------- degree / histogram ----------------
__global__ void init_kernel(float* deg, int* hist, int n) {
    int i = blockIdx.x * blockDim.x + threadIdx.x;
    if (i < n) { deg[i] = 1.0f; hist[i] = 0; }
}
__global__ void deg_hist_kernel(const int* __restrict__ ei, const float* __restrict__ ew,
                                float* deg, int* hist, int e) {
    int idx = blockIdx.x * blockDim.x + threadIdx.x;
    if (idx < e) {
        int c = ei[e + idx];
        atomicAdd(&deg[c], ew[idx]);
        atomicAdd(&hist[c], 1);
    }
}
__global__ void deg_fin_kernel(float* deg, int n) {
    int i = blockIdx.x * blockDim.x + threadIdx.x;
    if (i < n) deg[i] = rsqrtf(deg[i]);
}

// ---------------- exclusive scan (3 kernels) ----------------
__global__ __launch_bounds__(1024) void scanA_kernel(const int* __restrict__ hist,
                                                     int* __restrict__ excl,
                                                     int* __restrict__ bsums, int n) {
    __shared__ int smw[32];
    int tid = threadIdx.x;
    int gid = blockIdx.x * 1024 + tid;
    int lane = tid & 31, wid = tid >> 5;
    int v = (gid < n) ? hist[gid] : 0;
    int x = v;
    #pragma unroll
    for (int o = 1; o < 32; o <<= 1) {
        int y = __shfl_up_sync(0xffffffffu, x, o);
        if (lane >= o) x += y;
    }
    if (lane == 31) smw[wid] = x;
    __syncthreads();
    if (wid == 0) {
        int s = smw[lane];
        #pragma unroll
        for (int o = 1; o < 32; o <<= 1) {
            int y = __shfl_up_sync(0xffffffffu, s, o);
            if (lane >= o) s += y;
        }
        smw[lane] = s;
    }
    __syncthreads();
    int woff = (wid > 0) ? smw[wid - 1] : 0;
    int incl = x + woff;
    if (gid <= n) excl[gid] = incl - v;           // block-local exclusive
    if (tid == 1023) bsums[blockIdx.x] = incl;    // block total
}
__global__ void scanB_kernel(int* bsums, int nb) {
    if (threadIdx.x == 0) {
        int acc = 0;
        for (int i = 0; i < nb; i++) { int t = bsums[i]; bsums[i] = acc; acc += t; }
    }
}
__global__ void scanC_kernel(int* __restrict__ rowptr, int* __restrict__ cursor,
                             const int* __restrict__ bsums, int n, int e) {
    int gid = blockIdx.x * 1024 + threadIdx.x;
    if (gid < n) {
        int v = rowptr[gid] + bsums[blockIdx.x];
        rowptr[gid] = v;
        cursor[gid] = v;
    }
    if (gid == 0) rowptr[n] = e;
}

// ---------------- CSR fill: csr[pos] = {src, u = dinv[src]*ew} ----------------
__global__ void fill_kernel(const int* __restrict__ ei, const float* __restrict__ ew,
                            const float* __restrict__ dinv,
                            int* __restrict__ cursor, int2* __restrict__ csr, int e) {
    int idx = blockIdx.x * blockDim.x + threadIdx.x;
    if (idx < e) {
        int r = ei[idx];
        int c = ei[e + idx];
        int pos = atomicAdd(&cursor[c], 1);
        csr[pos] = make_int2(r, __float_as_int(dinv[r] * ew[idx]));
    }
}

// ---------------- weight bf16 split ----------------
__global__ void split_B1_kernel(const float* __restrict__ W1, const float* __restrict__ Wres,
                                uint32_t* __restrict__ hi, uint32_t* __restrict__ lo) {
    int idx = blockIdx.x * blockDim.x + threadIdx.x;    // 32768; idx = n*128 + p
    int nn = idx >> 7, p = idx & 127;
    float v0, v1;
    if (nn < 128) { v0 = W1[(2 * p) * 128 + nn];          v1 = W1[(2 * p + 1) * 128 + nn]; }
    else          { v0 = Wres[(2 * p) * 128 + nn - 128];  v1 = Wres[(2 * p + 1) * 128 + nn - 128]; }
    uint32_t h, l;
    split_pair(v0, v1, h, l);
    hi[idx] = h; lo[idx] = l;
}
__global__ void split_B2_kernel(const float* __restrict__ W2,
                                uint32_t* __restrict__ hi, uint32_t* __restrict__ lo) {
    int idx = blockIdx.x * blockDim.x + threadIdx.x;    // 8192; idx = n*64 + p
    int nn = idx >> 6, p = idx & 63;
    float v0 = W2[(2 * p) * 128 + nn];
    float v1 = W2[(2 * p + 1) * 128 + nn];
    uint32_t h, l;
    split_pair(v0, v1, h, l);
    hi[idx] = h; lo[idx] = l;
}
__global__ void bn_pre_kernel(const float* b1, const float* g1, const float* be1,
                              const float* m1, const float* v1,
                              const float* b2, const float* g2, const float* be2,
                              const float* m2, const float* v2,
                              float* sc1, float* sh1, float* sc2, float* sh2) {
    int f = threadIdx.x;
    float s1 = g1[f] * rsqrtf(v1[f] + BN_EPS);
    sc1[f] = s1;
    sh1[f] = (b1[f] - m1[f]) * s1 + be1[f];
    float s2 = g2[f] * rsqrtf(v2[f] + BN_EPS);
    sc2[f] = s2;
    sh2[f] = (b2[f] - m2[f]) * s2 + be2[f];
}

// ====== bf16 3x-split MMA GEMM: [C0|C1][M,128 each] = A[M,K] @ B ([Ntot][K/2] pairs) ======
#define PSTRIDE 20
__global__ __launch_bounds__(256) void mma_gemm_kernel(
    const float* __restrict__ A,
    const uint32_t* __restrict__ Bhi, const uint32_t* __restrict__ Blo,
    float* __restrict__ C0, float* __restrict__ C1, int M, int K) {
    __shared__ uint32_t AsH[128 * PSTRIDE];
    __shared__ uint32_t AsL[128 * PSTRIDE];
    __shared__ uint32_t BsH[128 * PSTRIDE];
    __shared__ uint32_t BsL[128 * PSTRIDE];

    const int tid = threadIdx.x;
    const int warpId = tid >> 5, lane = tid & 31;
    const int groupID = lane >> 2, tig = lane & 3;
    const int warpM = warpId & 3, warpN = warpId >> 2;
    const int m0 = blockIdx.y * 128;
    const int n0 = blockIdx.x * 128;
    const int Kp = K >> 1;
    float* Csel = (n0 == 0) ? C0 : C1;

    float acc[2][8][4];
    #pragma unroll
    for (int i = 0; i < 2; i++)
        #pragma unroll
        for (int j = 0; j < 8; j++)
            #pragma unroll
            for (int q = 0; q < 4; q++) acc[i][j][q] = 0.f;

    const int nChunks = K >> 5;
    for (int c = 0; c < nChunks; c++) {
        #pragma unroll
        for (int t = 0; t < 4; t++) {
            int idx = tid + t * 256;
            int row = idx >> 3;
            int cf = (idx & 7) * 4;
            int gr = m0 + row; if (gr >= M) gr = M - 1;
            float4 v = *(const float4*)(A + (size_t)gr * K + c * 32 + cf);
            uint2 h2, l2;
            split_pair(v.x, v.y, h2.x, l2.x);
            split_pair(v.z, v.w, h2.y, l2.y);
            int so = row * PSTRIDE + (cf >> 1);
            *(uint2*)&AsH[so] = h2;
            *(uint2*)&AsL[so] = l2;
        }
        #pragma unroll
        for (int t = 0; t < 2; t++) {
            int idx = tid + t * 256;
            int nn = idx >> 2;
            int q = (idx & 3) * 4;
            size_t go = (size_t)(n0 + nn) * Kp + c * 16 + q;
            int so = nn * PSTRIDE + q;
            *(uint4*)&BsH[so] = *(const uint4*)(Bhi + go);
            *(uint4*)&BsL[so] = *(const uint4*)(Blo + go);
        }
        __syncthreads();

        #pragma unroll
        for (int s = 0; s < 2; s++) {
            const int kp = s * 8 + tig;
            uint32_t ah[2][4], al[2][4];
            #pragma unroll
            for (int mt = 0; mt < 2; mt++) {
                int mb = warpM * 32 + mt * 16 + groupID;
                ah[mt][0] = AsH[mb * PSTRIDE + kp];
                ah[mt][1] = AsH[(mb + 8) * PSTRIDE + kp];
                ah[mt][2] = AsH[mb * PSTRIDE + kp + 4];
                ah[mt][3] = AsH[(mb + 8) * PSTRIDE + kp + 4];
                al[mt][0] = AsL[mb * PSTRIDE + kp];
                al[mt][1] = AsL[(mb + 8) * PSTRIDE + kp];
                al[mt][2] = AsL[mb * PSTRIDE + kp + 4];
                al[mt][3] = AsL[(mb + 8) * PSTRIDE + kp + 4];
            }
            #pragma unroll
            for (int nt = 0; nt < 8; nt++) {
                int nb = warpN * 64 + nt * 8 + groupID;
                uint32_t bh0 = BsH[nb * PSTRIDE + kp];
                uint32_t bh1 = BsH[nb * PSTRIDE + kp + 4];
                uint32_t bl0 = BsL[nb * PSTRIDE + kp];
                uint32_t bl1 = BsL[nb * PSTRIDE + kp + 4];
                #pragma unroll
                for (int mt = 0; mt < 2; mt++) {
                    mma_bf16(acc[mt][nt], ah[mt], bh0, bh1);
                    mma_bf16(acc[mt][nt], ah[mt], bl0, bl1);
                    mma_bf16(acc[mt][nt], al[mt], bh0, bh1);
                }
            }
        }
        __syncthreads();
    }

    #pragma unroll
    for (int mt = 0; mt < 2; mt++) {
        int row = m0 + warpM * 32 + mt * 16 + groupID;
        int row2 = row + 8;
        #pragma unroll
        for (int nt = 0; nt < 8; nt++) {
            int col = warpN * 64 + nt * 8 + tig * 2;     // local 0..127
            if (row < M)
                *(float2*)(Csel + (size_t)row * H_DIM + col) =
                    make_float2(acc[mt][nt][0], acc[mt][nt][1]);
            if (row2 < M)
                *(float2*)(Csel + (size_t)row2 * H_DIM + col) =
                    make_float2(acc[mt][nt][2], acc[mt][nt][3]);
        }
    }
}

// ====== CSR gather-aggregate (128-wide): warp per dst ======
// dst[i,:] = dinv[i] * ( sum_e u[e]*src[srcIdx[e],:] + dinv[i]*src[i,:] )
// optional BN+ReLU epilogue (layer 1).
__global__ __launch_bounds__(256) void agg_feat_kernel(
    const int* __restrict__ rowptr, const int2* __restrict__ csr,
    const float* __restrict__ src, const float* __restrict__ dinv,
    float* __restrict__ dst,
    const float* __restrict__ bnSc, const float* __restrict__ bnSh, int n) {
    int i = (blockIdx.x * blockDim.x + threadIdx.x) >> 5;
    int lane = threadIdx.x & 31;
    if (i >= n) return;
    int p = rowptr[i], pEnd = rowptr[i + 1];
    float di = dinv[i];
    float4 acc = *(const float4*)(src + (size_t)i * H_DIM + lane * 4);
    acc.x *= di; acc.y *= di; acc.z *= di; acc.w *= di;   // self term (x di again later)
    if (p < pEnd) {
        int2 e0 = csr[p];
        for (; p < pEnd; ) {
            int2 e1;
            if (p + 1 < pEnd) e1 = csr[p + 1];
            float u = __int_as_float(e0.y);
            float4 v = *(const float4*)(src + (size_t)e0.x * H_DIM + lane * 4);
            acc.x = fmaf(u, v.x, acc.x);
            acc.y = fmaf(u, v.y, acc.y);
            acc.z = fmaf(u, v.z, acc.z);
            acc.w = fmaf(u, v.w, acc.w);
            e0 = e1;
            p++;
        }
    }
    acc.x *= di; acc.y *= di; acc.z *= di; acc.w *= di;
    if (bnSc) {
        int f = lane * 4;
        float4 sc4 = *(const float4*)(bnSc + f);
        float4 sh4 = *(const float4*)(bnSh + f);
        acc.x = fmaxf(fmaf(acc.x, sc4.x, sh4.x), 0.f);
        acc.y = fmaxf(fmaf(acc.y, sc4.y, sh4.y), 0.f);
        acc.z = fmaxf(fmaf(acc.z, sc4.z, sh4.z), 0.f);
        acc.w = fmaxf(fmaf(acc.w, sc4.w, sh4.w), 0.f);
    }
    *(float4*)(dst + (size_t)i * H_DIM + lane * 4) = acc;
}

// ====== layer-2 aggregate + full epi2 fused: s[i] = relu(BN2(agg + res)) . W3 ======
__global__ __launch_bounds__(256) void agg2_epi_kernel(
    const int* __restrict__ rowptr, const int2* __restrict__ csr,
    const float* __restrict__ src, const float* __restrict__ res,
    const float* __restrict__ dinv,
    const float* __restrict__ sc2, const float* __restrict__ sh2,
    const float* __restrict__ W3, float* __restrict__ s, int n) {
    int i = (blockIdx.x * blockDim.x + threadIdx.x) >> 5;
    int lane = threadIdx.x & 31;
    if (i >= n) return;
    int p = rowptr[i], pEnd = rowptr[i + 1];
    float di = dinv[i];
    float4 acc = *(const float4*)(src + (size_t)i * H_DIM + lane * 4);
    acc.x *= di; acc.y *= di; acc.z *= di; acc.w *= di;
    if (p < pEnd) {
        int2 e0 = csr[p];
        for (; p < pEnd; ) {
            int2 e1;
            if (p + 1 < pEnd) e1 = csr[p + 1];
            float u = __int_as_float(e0.y);
            float4 v = *(const float4*)(src + (size_t)e0.x * H_DIM + lane * 4);
            acc.x = fmaf(u, v.x, acc.x);
            acc.y = fmaf(u, v.y, acc.y);
            acc.z = fmaf(u, v.z, acc.z);
            acc.w = fmaf(u, v.w, acc.w);
            e0 = e1;
            p++;
        }
    }
    int f = lane * 4;
    float4 r4  = *(const float4*)(res + (size_t)i * H_DIM + f);
    float4 sc4 = *(const float4*)(sc2 + f);
    float4 sh4 = *(const float4*)(sh2 + f);
    float4 w4  = *(const float4*)(W3 + f);
    float dot = 0.f;
    dot += fmaxf(fmaf(acc.x * di + r4.x, sc4.x, sh4.x), 0.f) * w4.x;
    dot += fmaxf(fmaf(acc.y * di + r4.y, sc4.y, sh4.y), 0.f) * w4.y;
    dot += fmaxf(fmaf(acc.z * di + r4.z, sc4.z, sh4.z), 0.f) * w4.z;
    dot += fmaxf(fmaf(acc.w * di + r4.w, sc4.w, sh4.w), 0.f) * w4.w;
    #pragma unroll
    for (int off = 16; off; off >>= 1)
        dot += __shfl_down_sync(0xffffffffu, dot, off);
    if (lane == 0) s[i] = dot;
}

// ====== layer-3 scalar aggregate: out[i] = dinv[i]*(sum u*s[src] + dinv[i]*s[i]) + b3 ======
__global__ void agg3_kernel(const int* __restrict__ rowptr, const int2* __restrict__ csr,
                            const float* __restrict__ s, const float* __restrict__ dinv,
                            const float* __restrict__ b3, float* __restrict__ out, int n) {
    int i = blockIdx.x * blockDim.x + threadIdx.x;
    if (i >= n) return;
    int p = rowptr[i], pEnd = rowptr[i + 1];
    float di = dinv[i];
    float acc = di * s[i];
    for (; p < pEnd; p++) {
        int2 e = csr[p];
        acc = fmaf(__int_as_float(e.y), s[e.x], acc);
    }
    out[i] = fmaf(di, acc, b3[0]);
}

// ---------------- launch ----------------
extern "C" void kernel_launch(void* const* d_in, const int* in_sizes, int n_in,
                              void* d_out, int out_size) {
    const float* x    = (const float*)d_in[0];
    const int*   ei   = (const int*)d_in[1];     // int32 (jax downcasts int64)
    const float* ew   = (const float*)d_in[2];
    const float* W1   = (const float*)d_in[3];
    const float* b1   = (const float*)d_in[4];
    const float* W2   = (const float*)d_in[5];
    const float* b2   = (const float*)d_in[6];
    const float* W3   = (const float*)d_in[7];
    const float* b3   = (const float*)d_in[8];
    const float* Wres = (const float*)d_in[9];
    const float* g1   = (const float*)d_in[10];
    const float* be1  = (const float*)d_in[11];
    const float* m1   = (const float*)d_in[12];
    const float* v1   = (const float*)d_in[13];
    const float* g2   = (const float*)d_in[14];
    const float* be2  = (const float*)d_in[15];
    const float* m2   = (const float*)d_in[16];
    const float* v2   = (const float*)d_in[17];
    float* out = (float*)d_out;

    int n = in_sizes[0] / V_IN;   // 100000
    int e = in_sizes[2];          // 1600000

    float *deg, *bufE, *bufR, *bufB, *bufC, *s, *sc1, *sh1, *sc2, *sh2;
    int *hist, *rowptr, *cursor, *bsums;
    int2 *csr;
    uint32_t *B1hi, *B1lo, *B2hi, *B2lo;
    cudaGetSymbolAddress((void**)&deg,    g_deg);
    cudaGetSymbolAddress((void**)&hist,   g_hist);
    cudaGetSymbolAddress((void**)&rowptr, g_rowptr);
    cudaGetSymbolAddress((void**)&cursor, g_cursor);
    cudaGetSymbolAddress((void**)&bsums,  g_bsums);
    cudaGetSymbolAddress((void**)&csr,    g_csr);
    cudaGetSymbolAddress((void**)&bufE,   g_bufE);
    cudaGetSymbolAddress((void**)&bufR,   g_bufR);
    cudaGetSymbolAddress((void**)&bufB,   g_bufB);
    cudaGetSymbolAddress((void**)&bufC,   g_bufC);
    cudaGetSymbolAddress((void**)&s,      g_s);
    cudaGetSymbolAddress((void**)&B1hi,   g_B1hi);
    cudaGetSymbolAddress((void**)&B1lo,   g_B1lo);
    cudaGetSymbolAddress((void**)&B2hi,   g_B2hi);
    cudaGetSymbolAddress((void**)&B2lo,   g_B2lo);
    cudaGetSymbolAddress((void**)&sc1,    g_sc1);
    cudaGetSymbolAddress((void**)&sh1,    g_sh1);
    cudaGetSymbolAddress((void**)&sc2,    g_sc2);
    cudaGetSymbolAddress((void**)&sh2,    g_sh2);

    int nb_n   = (n + 255) / 256;
    int nb_e   = (e + 255) / 256;
    int nb_nw  = (n + 7) / 8;                 // warp per node
    int nbScan = (n + 1023) / 1024;           // 98
    int mTiles = (n + 127) / 128;

    // degree + histogram
    init_kernel<<<nb_n, 256>>>(deg, hist, n);
    deg_hist_kernel<<<nb_e, 256>>>(ei, ew, deg, hist, e);
    deg_fin_kernel<<<nb_n, 256>>>(deg, n);

    // exclusive scan -> rowptr, cursor
    scanA_kernel<<<nbScan, 1024>>>(hist, rowptr, bsums, n);
    scanB_kernel<<<1, 32>>>(bsums, nbScan);
    scanC_kernel<<<nbScan, 1024>>>(rowptr, cursor, bsums, n, e);

    // CSR fill (u = dinv[src]*ew)
    fill_kernel<<<nb_e, 256>>>(ei, ew, deg, cursor, csr, e);

    // weight bf16 split, BN scale/shift
    split_B1_kernel<<<128, 256>>>(W1, Wres, B1hi, B1lo);
    split_B2_kernel<<<32, 256>>>(W2, B2hi, B2lo);
    bn_pre_kernel<<<1, 128>>>(b1, g1, be1, m1, v1, b2, g2, be2, m2, v2,
                              sc1, sh1, sc2, sh2);

    // GEMM1: bufE = x@W1, bufR = x@Wres (both contiguous [N,128])
    mma_gemm_kernel<<<dim3(2, mTiles), 256>>>(x, B1hi, B1lo, bufE, bufR, n, 256);

    // agg1 + BN1 + ReLU: bufB = relu(BN1(A_hat @ bufE))
    agg_feat_kernel<<<nb_nw, 256>>>(rowptr, csr, bufE, deg, bufB, sc1, sh1, n);

    // GEMM2: bufC = bufB @ W2
    mma_gemm_kernel<<<dim3(1, mTiles), 256>>>(bufB, B2hi, B2lo, bufC, nullptr, n, 128);

    // agg2 + BN2 + res + ReLU + .W3: s
    agg2_epi_kernel<<<nb_nw, 256>>>(rowptr, csr, bufC, bufR, deg, sc2, sh2, W3, s, n);

    // layer 3 scalar aggregate -> out
    agg3_kernel<<<nb_n, 256>>>(rowptr, csr, s, deg, b3, out, n);
}

// round 11
// speedup vs baseline: 2.5130x; 1.1090x over previous
#include <cuda_runtime.h>
#include <math.h>
#include <stdint.h>

#define N_NODES 100000
#define E_EDGES 1600000
#define V_IN    256
#define H_DIM   128
#define BN_EPS  1e-5f

// ---------------- scratch (static device globals; no allocs allowed) ----------------
__device__ __align__(16) float g_deg[N_NODES];                 // deg -> dinv (in place)
__device__ __align__(16) int   g_hist[N_NODES];                // in-degree histogram
__device__ __align__(16) int   g_rowptr[N_NODES + 1];          // CSR row pointers (by dst)
__device__ __align__(16) int   g_cursor[N_NODES];              // fill cursors
__device__ __align__(16) int   g_bsums[128];                   // scan block sums
__device__ __align__(16) int2  g_csr[E_EDGES];                 // {src, bitcast(u=dinv[src]*ew)}
__device__ __align__(16) float g_bufE[(size_t)N_NODES * H_DIM];// xW1 (contiguous)
__device__ __align__(16) float g_bufR[(size_t)N_NODES * H_DIM];// x Wres (residual)
__device__ __align__(16) float g_bufB[(size_t)N_NODES * H_DIM];// h1 = relu(BN1(out1))
__device__ __align__(16) float g_bufC[(size_t)N_NODES * H_DIM];// h1 @ W2
__device__ __align__(16) float g_s[N_NODES];                   // h2 @ W3
__device__ __align__(16) uint32_t g_B1hi[256 * 128];           // [W1|Wres] bf16-hi pairs [N][K/2]
__device__ __align__(16) uint32_t g_B1lo[256 * 128];
__device__ __align__(16) uint32_t g_B2hi[128 * 64];            // W2 pairs [N][K/2]
__device__ __align__(16) uint32_t g_B2lo[128 * 64];
__device__ __align__(16) float g_sc1[H_DIM];                   // BN1 scale (b1 folded)
__device__ __align__(16) float g_sh1[H_DIM];
__device__ __align__(16) float g_sc2[H_DIM];                   // BN2 scale (b2 folded)
__device__ __align__(16) float g_sh2[H_DIM];

// =================== bf16 split helpers ===================
__device__ __forceinline__ uint32_t pack_bf16x2(float x1, float x0) {
    uint32_t r;
    asm("cvt.rn.bf16x2.f32 %0, %1, %2;" : "=r"(r) : "f"(x1), "f"(x0));
    return r;
}
__device__ __forceinline__ float bf16_lo_f(uint32_t h) { return __uint_as_float(h << 16); }
__device__ __forceinline__ float bf16_hi_f(uint32_t h) { return __uint_as_float(h & 0xFFFF0000u); }
__device__ __forceinline__ void split_pair(float x0, float x1, uint32_t& hi, uint32_t& lo) {
    hi = pack_bf16x2(x1, x0);
    lo = pack_bf16x2(x1 - bf16_hi_f(hi), x0 - bf16_lo_f(hi));
}
__device__ __forceinline__ void mma_bf16(float* d, const uint32_t* a,
                                         uint32_t b0, uint32_t b1) {
    asm volatile(
        "mma.sync.aligned.m16n8k16.row.col.f32.bf16.bf16.f32 "
        "{%0,%1,%2,%3}, {%4,%5,%6,%7}, {%8,%9}, {%0,%1,%2,%3};"
        : "+f"(d[0]), "+f"(d[1]), "+f"(d[2]), "+f"(d[3])
        : "r"(a[0]), "r"(a[1]), "r"(a[2]), "r"(a[3]), "r"(b0), "r"(b1));
}

// ---------------- degree / histogram ----------------
__global__ void init_kernel(float* deg, int* hist, int n) {
    int i = blockIdx.x * blockDim.x + threadIdx.x;
    if (i < n) { deg[i] = 1.0f; hist[i] = 0; }
}
__global__ void deg_hist_kernel(const int* __restrict__ ei, const float* __restrict__ ew,
                                float* deg, int* hist, int e) {
    int idx = blockIdx.x * blockDim.x + threadIdx.x;
    if (idx < e) {
        int c = ei[e + idx];
        atomicAdd(&deg[c], ew[idx]);
        atomicAdd(&hist[c], 1);
    }
}
__global__ void deg_fin_kernel(float* deg, int n) {
    int i = blockIdx.x * blockDim.x + threadIdx.x;
    if (i < n) deg[i] = rsqrtf(deg[i]);
}

// ---------------- exclusive scan (3 kernels) ----------------
__global__ __launch_bounds__(1024) void scanA_kernel(const int* __restrict__ hist,
                                                     int* __restrict__ excl,
                                                     int* __restrict__ bsums, int n) {
    __shared__ int smw[32];
    int tid = threadIdx.x;
    int gid = blockIdx.x * 1024 + tid;
    int lane = tid & 31, wid = tid >> 5;
    int v = (gid < n) ? hist[gid] : 0;
    int x = v;
    #pragma unroll
    for (int o = 1; o < 32; o <<= 1) {
        int y = __shfl_up_sync(0xffffffffu, x, o);
        if (lane >= o) x += y;
    }
    if (lane == 31) smw[wid] = x;
    __syncthreads();
    if (wid == 0) {
        int s = smw[lane];
        #pragma unroll
        for (int o = 1; o < 32; o <<= 1) {
            int y = __shfl_up_sync(0xffffffffu, s, o);
            if (lane >= o) s += y;
        }
        smw[lane] = s;
    }
    __syncthreads();
    int woff = (wid > 0) ? smw[wid - 1] : 0;
    int incl = x + woff;
    if (gid <= n) excl[gid] = incl - v;           // block-local exclusive
    if (tid == 1023) bsums[blockIdx.x] = incl;    // block total
}
// parallel exclusive scan of <=128 block sums (one block, 128 threads)
__global__ void scanB_kernel(int* bsums, int nb) {
    __shared__ int ws[4];
    int tid = threadIdx.x;
    int lane = tid & 31, wid = tid >> 5;
    int v = (tid < nb) ? bsums[tid] : 0;
    int x = v;
    #pragma unroll
    for (int o = 1; o < 32; o <<= 1) {
        int y = __shfl_up_sync(0xffffffffu, x, o);
        if (lane >= o) x += y;
    }
    if (lane == 31) ws[wid] = x;
    __syncthreads();
    int add = 0;
    #pragma unroll
    for (int w = 0; w < 4; w++) add += (w < wid) ? ws[w] : 0;
    if (tid < nb) bsums[tid] = x + add - v;       // exclusive
}
__global__ void scanC_kernel(int* __restrict__ rowptr, int* __restrict__ cursor,
                             const int* __restrict__ bsums, int n, int e) {
    int gid = blockIdx.x * 1024 + threadIdx.x;
    if (gid < n) {
        int v = rowptr[gid] + bsums[blockIdx.x];
        rowptr[gid] = v;
        cursor[gid] = v;
    }
    if (gid == 0) rowptr[n] = e;
}

// ---------------- CSR fill: csr[pos] = {src, u = dinv[src]*ew} ----------------
__global__ void fill_kernel(const int* __restrict__ ei, const float* __restrict__ ew,
                            const float* __restrict__ dinv,
                            int* __restrict__ cursor, int2* __restrict__ csr, int e) {
    int idx = blockIdx.x * blockDim.x + threadIdx.x;
    if (idx < e) {
        int r = ei[idx];
        int c = ei[e + idx];
        int pos = atomicAdd(&cursor[c], 1);
        csr[pos] = make_int2(r, __float_as_int(dinv[r] * ew[idx]));
    }
}

// ---------------- weight bf16 split ----------------
__global__ void split_B1_kernel(const float* __restrict__ W1, const float* __restrict__ Wres,
                                uint32_t* __restrict__ hi, uint32_t* __restrict__ lo) {
    int idx = blockIdx.x * blockDim.x + threadIdx.x;    // 32768; idx = n*128 + p
    int nn = idx >> 7, p = idx & 127;
    float v0, v1;
    if (nn < 128) { v0 = W1[(2 * p) * 128 + nn];          v1 = W1[(2 * p + 1) * 128 + nn]; }
    else          { v0 = Wres[(2 * p) * 128 + nn - 128];  v1 = Wres[(2 * p + 1) * 128 + nn - 128]; }
    uint32_t h, l;
    split_pair(v0, v1, h, l);
    hi[idx] = h; lo[idx] = l;
}
__global__ void split_B2_kernel(const float* __restrict__ W2,
                                uint32_t* __restrict__ hi, uint32_t* __restrict__ lo) {
    int idx = blockIdx.x * blockDim.x + threadIdx.x;    // 8192; idx = n*64 + p
    int nn = idx >> 6, p = idx & 63;
    float v0 = W2[(2 * p) * 128 + nn];
    float v1 = W2[(2 * p + 1) * 128 + nn];
    uint32_t h, l;
    split_pair(v0, v1, h, l);
    hi[idx] = h; lo[idx] = l;
}
__global__ void bn_pre_kernel(const float* b1, const float* g1, const float* be1,
                              const float* m1, const float* v1,
                              const float* b2, const float* g2, const float* be2,
                              const float* m2, const float* v2,
                              float* sc1, float* sh1, float* sc2, float* sh2) {
    int f = threadIdx.x;
    float s1 = g1[f] * rsqrtf(v1[f] + BN_EPS);
    sc1[f] = s1;
    sh1[f] = (b1[f] - m1[f]) * s1 + be1[f];
    float s2 = g2[f] * rsqrtf(v2[f] + BN_EPS);
    sc2[f] = s2;
    sh2[f] = (b2[f] - m2[f]) * s2 + be2[f];
}

// ====== bf16 3x-split MMA GEMM: [C0|C1][M,128 each] = A[M,K] @ B ([Ntot][K/2] pairs) ======
#define PSTRIDE 20
__global__ __launch_bounds__(256) void mma_gemm_kernel(
    const float* __restrict__ A,
    const uint32_t* __restrict__ Bhi, const uint32_t* __restrict__ Blo,
    float* __restrict__ C0, float* __restrict__ C1, int M, int K) {
    __shared__ uint32_t AsH[128 * PSTRIDE];
    __shared__ uint32_t AsL[128 * PSTRIDE];
    __shared__ uint32_t BsH[128 * PSTRIDE];
    __shared__ uint32_t BsL[128 * PSTRIDE];

    const int tid = threadIdx.x;
    const int warpId = tid >> 5, lane = tid & 31;
    const int groupID = lane >> 2, tig = lane & 3;
    const int warpM = warpId & 3, warpN = warpId >> 2;
    const int m0 = blockIdx.y * 128;
    const int n0 = blockIdx.x * 128;
    const int Kp = K >> 1;
    float* Csel = (n0 == 0) ? C0 : C1;

    float acc[2][8][4];
    #pragma unroll
    for (int i = 0; i < 2; i++)
        #pragma unroll
        for (int j = 0; j < 8; j++)
            #pragma unroll
            for (int q = 0; q < 4; q++) acc[i][j][q] = 0.f;

    const int nChunks = K >> 5;
    for (int c = 0; c < nChunks; c++) {
        #pragma unroll
        for (int t = 0; t < 4; t++) {
            int idx = tid + t * 256;
            int row = idx >> 3;
            int cf = (idx & 7) * 4;
            int gr = m0 + row; if (gr >= M) gr = M - 1;
            float4 v = *(const float4*)(A + (size_t)gr * K + c * 32 + cf);
            uint2 h2, l2;
            split_pair(v.x, v.y, h2.x, l2.x);
            split_pair(v.z, v.w, h2.y, l2.y);
            int so = row * PSTRIDE + (cf >> 1);
            *(uint2*)&AsH[so] = h2;
            *(uint2*)&AsL[so] = l2;
        }
        #pragma unroll
        for (int t = 0; t < 2; t++) {
            int idx = tid + t * 256;
            int nn = idx >> 2;
            int q = (idx & 3) * 4;
            size_t go = (size_t)(n0 + nn) * Kp + c * 16 + q;
            int so = nn * PSTRIDE + q;
            *(uint4*)&BsH[so] = *(const uint4*)(Bhi + go);
            *(uint4*)&BsL[so] = *(const uint4*)(Blo + go);
        }
        __syncthreads();

        #pragma unroll
        for (int s = 0; s < 2; s++) {
            const int kp = s * 8 + tig;
            uint32_t ah[2][4], al[2][4];
            #pragma unroll
            for (int mt = 0; mt < 2; mt++) {
                int mb = warpM * 32 + mt * 16 + groupID;
                ah[mt][0] = AsH[mb * PSTRIDE + kp];
                ah[mt][1] = AsH[(mb + 8) * PSTRIDE + kp];
                ah[mt][2] = AsH[mb * PSTRIDE + kp + 4];
                ah[mt][3] = AsH[(mb + 8) * PSTRIDE + kp + 4];
                al[mt][0] = AsL[mb * PSTRIDE + kp];
                al[mt][1] = AsL[(mb + 8) * PSTRIDE + kp];
                al[mt][2] = AsL[mb * PSTRIDE + kp + 4];
                al[mt][3] = AsL[(mb + 8) * PSTRIDE + kp + 4];
            }
            #pragma unroll
            for (int nt = 0; nt < 8; nt++) {
                int nb = warpN * 64 + nt * 8 + groupID;
                uint32_t bh0 = BsH[nb * PSTRIDE + kp];
                uint32_t bh1 = BsH[nb * PSTRIDE + kp + 4];
                uint32_t bl0 = BsL[nb * PSTRIDE + kp];
                uint32_t bl1 = BsL[nb * PSTRIDE + kp + 4];
                #pragma unroll
                for (int mt = 0; mt < 2; mt++) {
                    mma_bf16(acc[mt][nt], ah[mt], bh0, bh1);
                    mma_bf16(acc[mt][nt], ah[mt], bl0, bl1);
                    mma_bf16(acc[mt][nt], al[mt], bh0, bh1);
                }
            }
        }
        __syncthreads();
    }

    #pragma unroll
    for (int mt = 0; mt < 2; mt++) {
        int row = m0 + warpM * 32 + mt * 16 + groupID;
        int row2 = row + 8;
        #pragma unroll
        for (int nt = 0; nt < 8; nt++) {
            int col = warpN * 64 + nt * 8 + tig * 2;     // local 0..127
            if (row < M)
                *(float2*)(Csel + (size_t)row * H_DIM + col) =
                    make_float2(acc[mt][nt][0], acc[mt][nt][1]);
            if (row2 < M)
                *(float2*)(Csel + (size_t)row2 * H_DIM + col) =
                    make_float2(acc[mt][nt][2], acc[mt][nt][3]);
        }
    }
}

// ====== CSR gather-aggregate (128-wide): warp per dst, warp-batched CSR loads ======
__global__ __launch_bounds__(256) void agg_feat_kernel(
    const int* __restrict__ rowptr, const int2* __restrict__ csr,
    const float* __restrict__ src, const float* __restrict__ dinv,
    float* __restrict__ dst,
    const float* __restrict__ bnSc, const float* __restrict__ bnSh, int n) {
    int i = (blockIdx.x * blockDim.x + threadIdx.x) >> 5;
    int lane = threadIdx.x & 31;
    if (i >= n) return;
    int p = rowptr[i], pEnd = rowptr[i + 1];
    float di = dinv[i];
    float4 acc = *(const float4*)(src + (size_t)i * H_DIM + lane * 4);
    acc.x *= di; acc.y *= di; acc.z *= di; acc.w *= di;   // self term
    float4 acc2 = make_float4(0.f, 0.f, 0.f, 0.f);
    const unsigned FULL = 0xffffffffu;
    while (p < pEnd) {
        int take = pEnd - p; if (take > 32) take = 32;
        int2 ce = make_int2(0, 0);
        if (lane < take) ce = csr[p + lane];
        int j = 0;
        for (; j + 2 <= take; j += 2) {
            int s0 = __shfl_sync(FULL, ce.x, j);
            float u0 = __int_as_float(__shfl_sync(FULL, ce.y, j));
            int s1 = __shfl_sync(FULL, ce.x, j + 1);
            float u1 = __int_as_float(__shfl_sync(FULL, ce.y, j + 1));
            float4 v0 = *(const float4*)(src + (size_t)s0 * H_DIM + lane * 4);
            float4 v1 = *(const float4*)(src + (size_t)s1 * H_DIM + lane * 4);
            acc.x = fmaf(u0, v0.x, acc.x);  acc2.x = fmaf(u1, v1.x, acc2.x);
            acc.y = fmaf(u0, v0.y, acc.y);  acc2.y = fmaf(u1, v1.y, acc2.y);
            acc.z = fmaf(u0, v0.z, acc.z);  acc2.z = fmaf(u1, v1.z, acc2.z);
            acc.w = fmaf(u0, v0.w, acc.w);  acc2.w = fmaf(u1, v1.w, acc2.w);
        }
        if (j < take) {
            int s0 = __shfl_sync(FULL, ce.x, j);
            float u0 = __int_as_float(__shfl_sync(FULL, ce.y, j));
            float4 v0 = *(const float4*)(src + (size_t)s0 * H_DIM + lane * 4);
            acc.x = fmaf(u0, v0.x, acc.x);
            acc.y = fmaf(u0, v0.y, acc.y);
            acc.z = fmaf(u0, v0.z, acc.z);
            acc.w = fmaf(u0, v0.w, acc.w);
        }
        p += take;
    }
    acc.x = (acc.x + acc2.x) * di;
    acc.y = (acc.y + acc2.y) * di;
    acc.z = (acc.z + acc2.z) * di;
    acc.w = (acc.w + acc2.w) * di;
    if (bnSc) {
        int f = lane * 4;
        float4 sc4 = *(const float4*)(bnSc + f);
        float4 sh4 = *(const float4*)(bnSh + f);
        acc.x = fmaxf(fmaf(acc.x, sc4.x, sh4.x), 0.f);
        acc.y = fmaxf(fmaf(acc.y, sc4.y, sh4.y), 0.f);
        acc.z = fmaxf(fmaf(acc.z, sc4.z, sh4.z), 0.f);
        acc.w = fmaxf(fmaf(acc.w, sc4.w, sh4.w), 0.f);
    }
    *(float4*)(dst + (size_t)i * H_DIM + lane * 4) = acc;
}

// ====== layer-2 aggregate + full epi2 fused: s[i] = relu(BN2(agg + res)) . W3 ======
__global__ __launch_bounds__(256) void agg2_epi_kernel(
    const int* __restrict__ rowptr, const int2* __restrict__ csr,
    const float* __restrict__ src, const float* __restrict__ res,
    const float* __restrict__ dinv,
    const float* __restrict__ sc2, const float* __restrict__ sh2,
    const float* __restrict__ W3, float* __restrict__ s, int n) {
    int i = (blockIdx.x * blockDim.x + threadIdx.x) >> 5;
    int lane = threadIdx.x & 31;
    if (i >= n) return;
    int p = rowptr[i], pEnd = rowptr[i + 1];
    float di = dinv[i];
    float4 acc = *(const float4*)(src + (size_t)i * H_DIM + lane * 4);
    acc.x *= di; acc.y *= di; acc.z *= di; acc.w *= di;
    float4 acc2 = make_float4(0.f, 0.f, 0.f, 0.f);
    const unsigned FULL = 0xffffffffu;
    while (p < pEnd) {
        int take = pEnd - p; if (take > 32) take = 32;
        int2 ce = make_int2(0, 0);
        if (lane < take) ce = csr[p + lane];
        int j = 0;
        for (; j + 2 <= take; j += 2) {
            int s0 = __shfl_sync(FULL, ce.x, j);
            float u0 = __int_as_float(__shfl_sync(FULL, ce.y, j));
            int s1 = __shfl_sync(FULL, ce.x, j + 1);
            float u1 = __int_as_float(__shfl_sync(FULL, ce.y, j + 1));
            float4 v0 = *(const float4*)(src + (size_t)s0 * H_DIM + lane * 4);
            float4 v1 = *(const float4*)(src + (size_t)s1 * H_DIM + lane * 4);
            acc.x = fmaf(u0, v0.x, acc.x);  acc2.x = fmaf(u1, v1.x, acc2.x);
            acc.y = fmaf(u0, v0.y, acc.y);  acc2.y = fmaf(u1, v1.y, acc2.y);
            acc.z = fmaf(u0, v0.z, acc.z);  acc2.z = fmaf(u1, v1.z, acc2.z);
            acc.w = fmaf(u0, v0.w, acc.w);  acc2.w = fmaf(u1, v1.w, acc2.w);
        }
        if (j < take) {
            int s0 = __shfl_sync(FULL, ce.x, j);
            float u0 = __int_as_float(__shfl_sync(FULL, ce.y, j));
            float4 v0 = *(const float4*)(src + (size_t)s0 * H_DIM + lane * 4);
            acc.x = fmaf(u0, v0.x, acc.x);
            acc.y = fmaf(u0, v0.y, acc.y);
            acc.z = fmaf(u0, v0.z, acc.z);
            acc.w = fmaf(u0, v0.w, acc.w);
        }
        p += take;
    }
    acc.x += acc2.x; acc.y += acc2.y; acc.z += acc2.z; acc.w += acc2.w;
    int f = lane * 4;
    float4 r4  = *(const float4*)(res + (size_t)i * H_DIM + f);
    float4 sc4 = *(const float4*)(sc2 + f);
    float4 sh4 = *(const float4*)(sh2 + f);
    float4 w4  = *(const float4*)(W3 + f);
    float dot = 0.f;
    dot += fmaxf(fmaf(acc.x * di + r4.x, sc4.x, sh4.x), 0.f) * w4.x;
    dot += fmaxf(fmaf(acc.y * di + r4.y, sc4.y, sh4.y), 0.f) * w4.y;
    dot += fmaxf(fmaf(acc.z * di + r4.z, sc4.z, sh4.z), 0.f) * w4.z;
    dot += fmaxf(fmaf(acc.w * di + r4.w, sc4.w, sh4.w), 0.f) * w4.w;
    #pragma unroll
    for (int off = 16; off; off >>= 1)
        dot += __shfl_down_sync(FULL, dot, off);
    if (lane == 0) s[i] = dot;
}

// ====== layer-3 scalar aggregate: out[i] = dinv[i]*(sum u*s[src] + dinv[i]*s[i]) + b3 ======
__global__ void agg3_kernel(const int* __restrict__ rowptr, const int2* __restrict__ csr,
                            const float* __restrict__ s, const float* __restrict__ dinv,
                            const float* __restrict__ b3, float* __restrict__ out, int n) {
    int i = blockIdx.x * blockDim.x + threadIdx.x;
    if (i >= n) return;
    int p = rowptr[i], pEnd = rowptr[i + 1];
    float di = dinv[i];
    float acc = di * s[i];
    for (; p < pEnd; p++) {
        int2 e = csr[p];
        acc = fmaf(__int_as_float(e.y), s[e.x], acc);
    }
    out[i] = fmaf(di, acc, b3[0]);
}

// ---------------- launch ----------------
extern "C" void kernel_launch(void* const* d_in, const int* in_sizes, int n_in,
                              void* d_out, int out_size) {
    const float* x    = (const float*)d_in[0];
    const int*   ei   = (const int*)d_in[1];     // int32 (jax downcasts int64)
    const float* ew   = (const float*)d_in[2];
    const float* W1   = (const float*)d_in[3];
    const float* b1   = (const float*)d_in[4];
    const float* W2   = (const float*)d_in[5];
    const float* b2   = (const float*)d_in[6];
    const float* W3   = (const float*)d_in[7];
    const float* b3   = (const float*)d_in[8];
    const float* Wres = (const float*)d_in[9];
    const float* g1   = (const float*)d_in[10];
    const float* be1  = (const float*)d_in[11];
    const float* m1   = (const float*)d_in[12];
    const float* v1   = (const float*)d_in[13];
    const float* g2   = (const float*)d_in[14];
    const float* be2  = (const float*)d_in[15];
    const float* m2   = (const float*)d_in[16];
    const float* v2   = (const float*)d_in[17];
    float* out = (float*)d_out;

    int n = in_sizes[0] / V_IN;   // 100000
    int e = in_sizes[2];          // 1600000

    float *deg, *bufE, *bufR, *bufB, *bufC, *s, *sc1, *sh1, *sc2, *sh2;
    int *hist, *rowptr, *cursor, *bsums;
    int2 *csr;
    uint32_t *B1hi, *B1lo, *B2hi, *B2lo;
    cudaGetSymbolAddress((void**)&deg,    g_deg);
    cudaGetSymbolAddress((void**)&hist,   g_hist);
    cudaGetSymbolAddress((void**)&rowptr, g_rowptr);
    cudaGetSymbolAddress((void**)&cursor, g_cursor);
    cudaGetSymbolAddress((void**)&bsums,  g_bsums);
    cudaGetSymbolAddress((void**)&csr,    g_csr);
    cudaGetSymbolAddress((void**)&bufE,   g_bufE);
    cudaGetSymbolAddress((void**)&bufR,   g_bufR);
    cudaGetSymbolAddress((void**)&bufB,   g_bufB);
    cudaGetSymbolAddress((void**)&bufC,   g_bufC);
    cudaGetSymbolAddress((void**)&s,      g_s);
    cudaGetSymbolAddress((void**)&B1hi,   g_B1hi);
    cudaGetSymbolAddress((void**)&B1lo,   g_B1lo);
    cudaGetSymbolAddress((void**)&B2hi,   g_B2hi);
    cudaGetSymbolAddress((void**)&B2lo,   g_B2lo);
    cudaGetSymbolAddress((void**)&sc1,    g_sc1);
    cudaGetSymbolAddress((void**)&sh1,    g_sh1);
    cudaGetSymbolAddress((void**)&sc2,    g_sc2);
    cudaGetSymbolAddress((void**)&sh2,    g_sh2);

    int nb_n   = (n + 255) / 256;
    int nb_e   = (e + 255) / 256;
    int nb_nw  = (n + 7) / 8;                 // warp per node
    int nbScan = (n + 1023) / 1024;           // 98
    int mTiles = (n + 127) / 128;

    // streams/events for graph-parallel branches (host objects; created once)
    static cudaStream_t st1 = nullptr, st2 = nullptr;
    static cudaEvent_t evRoot = nullptr, evCsr = nullptr, evSmall = nullptr;
    if (!st1) {
        cudaStreamCreateWithFlags(&st1, cudaStreamNonBlocking);
        cudaStreamCreateWithFlags(&st2, cudaStreamNonBlocking);
        cudaEventCreateWithFlags(&evRoot,  cudaEventDisableTiming);
        cudaEventCreateWithFlags(&evCsr,   cudaEventDisableTiming);
        cudaEventCreateWithFlags(&evSmall, cudaEventDisableTiming);
    }

    // fork
    cudaEventRecord(evRoot, 0);
    cudaStreamWaitEvent(st1, evRoot, 0);
    cudaStreamWaitEvent(st2, evRoot, 0);

    // branch st1: CSR build chain
    init_kernel<<<nb_n, 256, 0, st1>>>(deg, hist, n);
    deg_hist_kernel<<<nb_e, 256, 0, st1>>>(ei, ew, deg, hist, e);
    deg_fin_kernel<<<nb_n, 256, 0, st1>>>(deg, n);
    scanA_kernel<<<nbScan, 1024, 0, st1>>>(hist, rowptr, bsums, n);
    scanB_kernel<<<1, 128, 0, st1>>>(bsums, nbScan);
    scanC_kernel<<<nbScan, 1024, 0, st1>>>(rowptr, cursor, bsums, n, e);
    fill_kernel<<<nb_e, 256, 0, st1>>>(ei, ew, deg, cursor, csr, e);
    cudaEventRecord(evCsr, st1);

    // branch st2: small weight prep
    split_B2_kernel<<<32, 256, 0, st2>>>(W2, B2hi, B2lo);
    bn_pre_kernel<<<1, 128, 0, st2>>>(b1, g1, be1, m1, v1, b2, g2, be2, m2, v2,
                                      sc1, sh1, sc2, sh2);
    cudaEventRecord(evSmall, st2);

    // main branch: GEMM1 (independent of CSR)
    split_B1_kernel<<<128, 256>>>(W1, Wres, B1hi, B1lo);
    mma_gemm_kernel<<<dim3(2, mTiles), 256>>>(x, B1hi, B1lo, bufE, bufR, n, 256);

    // join
    cudaStreamWaitEvent(0, evCsr, 0);
    cudaStreamWaitEvent(0, evSmall, 0);

    // agg1 + BN1 + ReLU: bufB = relu(BN1(A_hat @ bufE))
    agg_feat_kernel<<<nb_nw, 256>>>(rowptr, csr, bufE, deg, bufB, sc1, sh1, n);

    // GEMM2: bufC = bufB @ W2
    mma_gemm_kernel<<<dim3(1, mTiles), 256>>>(bufB, B2hi, B2lo, bufC, nullptr, n, 128);

    // agg2 + BN2 + res + ReLU + .W3: s
    agg2_epi_kernel<<<nb_nw, 256>>>(rowptr, csr, bufC, bufR, deg, sc2, sh2, W3, s, n);

    // layer 3 scalar aggregate -> out
    agg3_kernel<<<nb_n, 256>>>(rowptr, csr, s, deg, b3, out, n);
}

// round 12
// speedup vs baseline: 3.2935x; 1.3106x over previous
#include <cuda_runtime.h>
#include <cuda_fp16.h>
#include <math.h>
#include <stdint.h>

#define N_NODES 100000
#define E_EDGES 1600000
#define V_IN    256
#define H_DIM   128
#define BN_EPS  1e-5f

// ---------------- scratch (static device globals; no allocs allowed) ----------------
__device__ __align__(16) float g_deg[N_NODES];                 // deg -> dinv (in place)
__device__ __align__(16) int   g_hist[N_NODES];
__device__ __align__(16) int   g_rowptr[N_NODES + 1];
__device__ __align__(16) int   g_cursor[N_NODES];
__device__ __align__(16) int   g_bsums[128];
__device__ __align__(16) int2  g_csr[E_EDGES];                 // {src, bitcast(u=dinv[src]*ew)}
__device__ __align__(16) __half2 g_bufE[(size_t)N_NODES * 64]; // xW1, fp16 pairs
__device__ __align__(16) float g_bufR[(size_t)N_NODES * H_DIM];// x Wres (residual, fp32)
__device__ __align__(16) float g_bufB[(size_t)N_NODES * H_DIM];// h1 = relu(BN1(out1)) fp32
__device__ __align__(16) __half2 g_bufC[(size_t)N_NODES * 64]; // h1@W2, fp16 pairs
__device__ __align__(16) float g_s[N_NODES];                   // h2 @ W3
__device__ __align__(16) uint32_t g_B1hi[256 * 128];           // [W1|Wres] bf16-hi pairs [N][K/2]
__device__ __align__(16) uint32_t g_B1lo[256 * 128];
__device__ __align__(16) uint32_t g_B2hi[128 * 64];
__device__ __align__(16) uint32_t g_B2lo[128 * 64];
__device__ __align__(16) float g_sc1[H_DIM];
__device__ __align__(16) float g_sh1[H_DIM];
__device__ __align__(16) float g_sc2[H_DIM];
__device__ __align__(16) float g_sh2[H_DIM];

// =================== bf16 split helpers ===================
__device__ __forceinline__ uint32_t pack_bf16x2(float x1, float x0) {
    uint32_t r;
    asm("cvt.rn.bf16x2.f32 %0, %1, %2;" : "=r"(r) : "f"(x1), "f"(x0));
    return r;
}
__device__ __forceinline__ float bf16_lo_f(uint32_t h) { return __uint_as_float(h << 16); }
__device__ __forceinline__ float bf16_hi_f(uint32_t h) { return __uint_as_float(h & 0xFFFF0000u); }
__device__ __forceinline__ void split_pair(float x0, float x1, uint32_t& hi, uint32_t& lo) {
    hi = pack_bf16x2(x1, x0);
    lo = pack_bf16x2(x1 - bf16_hi_f(hi), x0 - bf16_lo_f(hi));
}
__device__ __forceinline__ void mma_bf16(float* d, const uint32_t* a,
                                         uint32_t b0, uint32_t b1) {
    asm volatile(
        "mma.sync.aligned.m16n8k16.row.col.f32.bf16.bf16.f32 "
        "{%0,%1,%2,%3}, {%4,%5,%6,%7}, {%8,%9}, {%0,%1,%2,%3};"
        : "+f"(d[0]), "+f"(d[1]), "+f"(d[2]), "+f"(d[3])
        : "r"(a[0]), "r"(a[1]), "r"(a[2]), "r"(a[3]), "r"(b0), "r"(b1));
}

// ---------------- degree / histogram ----------------
__global__ void init_kernel(float* deg, int* hist, int n) {
    int i = blockIdx.x * blockDim.x + threadIdx.x;
    if (i < n) { deg[i] = 1.0f; hist[i] = 0; }
}
__global__ void deg_hist_kernel(const int* __restrict__ ei, const float* __restrict__ ew,
                                float* deg, int* hist, int e) {
    int idx = blockIdx.x * blockDim.x + threadIdx.x;
    if (idx < e) {
        int c = ei[e + idx];
        atomicAdd(&deg[c], ew[idx]);
        atomicAdd(&hist[c], 1);
    }
}
__global__ void deg_fin_kernel(float* deg, int n) {
    int i = blockIdx.x * blockDim.x + threadIdx.x;
    if (i < n) deg[i] = rsqrtf(deg[i]);
}

// ---------------- exclusive scan (3 kernels) ----------------
__global__ __launch_bounds__(1024) void scanA_kernel(const int* __restrict__ hist,
                                                     int* __restrict__ excl,
                                                     int* __restrict__ bsums, int n) {
    __shared__ int smw[32];
    int tid = threadIdx.x;
    int gid = blockIdx.x * 1024 + tid;
    int lane = tid & 31, wid = tid >> 5;
    int v = (gid < n) ? hist[gid] : 0;
    int x = v;
    #pragma unroll
    for (int o = 1; o < 32; o <<= 1) {
        int y = __shfl_up_sync(0xffffffffu, x, o);
        if (lane >= o) x += y;
    }
    if (lane == 31) smw[wid] = x;
    __syncthreads();
    if (wid == 0) {
        int s = smw[lane];
        #pragma unroll
        for (int o = 1; o < 32; o <<= 1) {
            int y = __shfl_up_sync(0xffffffffu, s, o);
            if (lane >= o) s += y;
        }
        smw[lane] = s;
    }
    __syncthreads();
    int woff = (wid > 0) ? smw[wid - 1] : 0;
    int incl = x + woff;
    if (gid <= n) excl[gid] = incl - v;
    if (tid == 1023) bsums[blockIdx.x] = incl;
}
__global__ void scanB_kernel(int* bsums, int nb) {
    __shared__ int ws[4];
    int tid = threadIdx.x;
    int lane = tid & 31, wid = tid >> 5;
    int v = (tid < nb) ? bsums[tid] : 0;
    int x = v;
    #pragma unroll
    for (int o = 1; o < 32; o <<= 1) {
        int y = __shfl_up_sync(0xffffffffu, x, o);
        if (lane >= o) x += y;
    }
    if (lane == 31) ws[wid] = x;
    __syncthreads();
    int add = 0;
    #pragma unroll
    for (int w = 0; w < 4; w++) add += (w < wid) ? ws[w] : 0;
    if (tid < nb) bsums[tid] = x + add - v;
}
__global__ void scanC_kernel(int* __restrict__ rowptr, int* __restrict__ cursor,
                             const int* __restrict__ bsums, int n, int e) {
    int gid = blockIdx.x * 1024 + threadIdx.x;
    if (gid < n) {
        int v = rowptr[gid] + bsums[blockIdx.x];
        rowptr[gid] = v;
        cursor[gid] = v;
    }
    if (gid == 0) rowptr[n] = e;
}

// ---------------- CSR fill ----------------
__global__ void fill_kernel(const int* __restrict__ ei, const float* __restrict__ ew,
                            const float* __restrict__ dinv,
                            int* __restrict__ cursor, int2* __restrict__ csr, int e) {
    int idx = blockIdx.x * blockDim.x + threadIdx.x;
    if (idx < e) {
        int r = ei[idx];
        int c = ei[e + idx];
        int pos = atomicAdd(&cursor[c], 1);
        csr[pos] = make_int2(r, __float_as_int(dinv[r] * ew[idx]));
    }
}

// ---------------- weight bf16 split ----------------
__global__ void split_B1_kernel(const float* __restrict__ W1, const float* __restrict__ Wres,
                                uint32_t* __restrict__ hi, uint32_t* __restrict__ lo) {
    int idx = blockIdx.x * blockDim.x + threadIdx.x;    // 32768
    int nn = idx >> 7, p = idx & 127;
    float v0, v1;
    if (nn < 128) { v0 = W1[(2 * p) * 128 + nn];          v1 = W1[(2 * p + 1) * 128 + nn]; }
    else          { v0 = Wres[(2 * p) * 128 + nn - 128];  v1 = Wres[(2 * p + 1) * 128 + nn - 128]; }
    uint32_t h, l;
    split_pair(v0, v1, h, l);
    hi[idx] = h; lo[idx] = l;
}
__global__ void split_B2_kernel(const float* __restrict__ W2,
                                uint32_t* __restrict__ hi, uint32_t* __restrict__ lo) {
    int idx = blockIdx.x * blockDim.x + threadIdx.x;    // 8192
    int nn = idx >> 6, p = idx & 63;
    float v0 = W2[(2 * p) * 128 + nn];
    float v1 = W2[(2 * p + 1) * 128 + nn];
    uint32_t h, l;
    split_pair(v0, v1, h, l);
    hi[idx] = h; lo[idx] = l;
}
__global__ void bn_pre_kernel(const float* b1, const float* g1, const float* be1,
                              const float* m1, const float* v1,
                              const float* b2, const float* g2, const float* be2,
                              const float* m2, const float* v2,
                              float* sc1, float* sh1, float* sc2, float* sh2) {
    int f = threadIdx.x;
    float s1 = g1[f] * rsqrtf(v1[f] + BN_EPS);
    sc1[f] = s1;
    sh1[f] = (b1[f] - m1[f]) * s1 + be1[f];
    float s2 = g2[f] * rsqrtf(v2[f] + BN_EPS);
    sc2[f] = s2;
    sh2[f] = (b2[f] - m2[f]) * s2 + be2[f];
}

// ====== bf16 3x-split MMA GEMM: A[M,K] @ B -> tile n0==0 to half2 Ch, n0==128 to fp32 Cf ======
#define PSTRIDE 20
__global__ __launch_bounds__(256) void mma_gemm_kernel(
    const float* __restrict__ A,
    const uint32_t* __restrict__ Bhi, const uint32_t* __restrict__ Blo,
    __half2* __restrict__ Ch, float* __restrict__ Cf, int M, int K) {
    __shared__ uint32_t AsH[128 * PSTRIDE];
    __shared__ uint32_t AsL[128 * PSTRIDE];
    __shared__ uint32_t BsH[128 * PSTRIDE];
    __shared__ uint32_t BsL[128 * PSTRIDE];

    const int tid = threadIdx.x;
    const int warpId = tid >> 5, lane = tid & 31;
    const int groupID = lane >> 2, tig = lane & 3;
    const int warpM = warpId & 3, warpN = warpId >> 2;
    const int m0 = blockIdx.y * 128;
    const int n0 = blockIdx.x * 128;
    const int Kp = K >> 1;

    float acc[2][8][4];
    #pragma unroll
    for (int i = 0; i < 2; i++)
        #pragma unroll
        for (int j = 0; j < 8; j++)
            #pragma unroll
            for (int q = 0; q < 4; q++) acc[i][j][q] = 0.f;

    const int nChunks = K >> 5;
    for (int c = 0; c < nChunks; c++) {
        #pragma unroll
        for (int t = 0; t < 4; t++) {
            int idx = tid + t * 256;
            int row = idx >> 3;
            int cf = (idx & 7) * 4;
            int gr = m0 + row; if (gr >= M) gr = M - 1;
            float4 v = *(const float4*)(A + (size_t)gr * K + c * 32 + cf);
            uint2 h2, l2;
            split_pair(v.x, v.y, h2.x, l2.x);
            split_pair(v.z, v.w, h2.y, l2.y);
            int so = row * PSTRIDE + (cf >> 1);
            *(uint2*)&AsH[so] = h2;
            *(uint2*)&AsL[so] = l2;
        }
        #pragma unroll
        for (int t = 0; t < 2; t++) {
            int idx = tid + t * 256;
            int nn = idx >> 2;
            int q = (idx & 3) * 4;
            size_t go = (size_t)(n0 + nn) * Kp + c * 16 + q;
            int so = nn * PSTRIDE + q;
            *(uint4*)&BsH[so] = *(const uint4*)(Bhi + go);
            *(uint4*)&BsL[so] = *(const uint4*)(Blo + go);
        }
        __syncthreads();

        #pragma unroll
        for (int s = 0; s < 2; s++) {
            const int kp = s * 8 + tig;
            uint32_t ah[2][4], al[2][4];
            #pragma unroll
            for (int mt = 0; mt < 2; mt++) {
                int mb = warpM * 32 + mt * 16 + groupID;
                ah[mt][0] = AsH[mb * PSTRIDE + kp];
                ah[mt][1] = AsH[(mb + 8) * PSTRIDE + kp];
                ah[mt][2] = AsH[mb * PSTRIDE + kp + 4];
                ah[mt][3] = AsH[(mb + 8) * PSTRIDE + kp + 4];
                al[mt][0] = AsL[mb * PSTRIDE + kp];
                al[mt][1] = AsL[(mb + 8) * PSTRIDE + kp];
                al[mt][2] = AsL[mb * PSTRIDE + kp + 4];
                al[mt][3] = AsL[(mb + 8) * PSTRIDE + kp + 4];
            }
            #pragma unroll
            for (int nt = 0; nt < 8; nt++) {
                int nb = warpN * 64 + nt * 8 + groupID;
                uint32_t bh0 = BsH[nb * PSTRIDE + kp];
                uint32_t bh1 = BsH[nb * PSTRIDE + kp + 4];
                uint32_t bl0 = BsL[nb * PSTRIDE + kp];
                uint32_t bl1 = BsL[nb * PSTRIDE + kp + 4];
                #pragma unroll
                for (int mt = 0; mt < 2; mt++) {
                    mma_bf16(acc[mt][nt], ah[mt], bh0, bh1);
                    mma_bf16(acc[mt][nt], ah[mt], bl0, bl1);
                    mma_bf16(acc[mt][nt], al[mt], bh0, bh1);
                }
            }
        }
        __syncthreads();
    }

    #pragma unroll
    for (int mt = 0; mt < 2; mt++) {
        int row = m0 + warpM * 32 + mt * 16 + groupID;
        int row2 = row + 8;
        #pragma unroll
        for (int nt = 0; nt < 8; nt++) {
            int col = warpN * 64 + nt * 8 + tig * 2;     // local 0..127
            if (n0 == 0) {
                if (row < M)
                    Ch[(size_t)row * 64 + (col >> 1)] =
                        __floats2half2_rn(acc[mt][nt][0], acc[mt][nt][1]);
                if (row2 < M)
                    Ch[(size_t)row2 * 64 + (col >> 1)] =
                        __floats2half2_rn(acc[mt][nt][2], acc[mt][nt][3]);
            } else {
                if (row < M)
                    *(float2*)(Cf + (size_t)row * H_DIM + col) =
                        make_float2(acc[mt][nt][0], acc[mt][nt][1]);
                if (row2 < M)
                    *(float2*)(Cf + (size_t)row2 * H_DIM + col) =
                        make_float2(acc[mt][nt][2], acc[mt][nt][3]);
            }
        }
    }
}

// ---- fp16 row gather helper: lane covers 4 floats (one uint2 = 2 half2) ----
__device__ __forceinline__ void h4_load(const __half2* __restrict__ base, int row, int lane,
                                        float2& a, float2& b) {
    uint2 raw = *((const uint2*)(base + (size_t)row * 64) + lane);
    a = __half22float2(*(__half2*)&raw.x);
    b = __half22float2(*(__half2*)&raw.y);
}

// ====== agg1 (fp16 src): bufB = relu(BN1(dinv*(sum u*srcRow + dinv*selfRow))) ======
__global__ __launch_bounds__(256) void agg_feat_kernel(
    const int* __restrict__ rowptr, const int2* __restrict__ csr,
    const __half2* __restrict__ src, const float* __restrict__ dinv,
    float* __restrict__ dst,
    const float* __restrict__ bnSc, const float* __restrict__ bnSh, int n) {
    int i = (blockIdx.x * blockDim.x + threadIdx.x) >> 5;
    int lane = threadIdx.x & 31;
    if (i >= n) return;
    int p = rowptr[i], pEnd = rowptr[i + 1];
    float di = dinv[i];
    float2 sa, sb;
    h4_load(src, i, lane, sa, sb);
    float4 acc = make_float4(sa.x * di, sa.y * di, sb.x * di, sb.y * di);
    float4 acc2 = make_float4(0.f, 0.f, 0.f, 0.f);
    const unsigned FULL = 0xffffffffu;
    while (p < pEnd) {
        int take = pEnd - p; if (take > 32) take = 32;
        int2 ce = make_int2(0, 0);
        if (lane < take) ce = csr[p + lane];
        int j = 0;
        for (; j + 4 <= take; j += 4) {
            int s0 = __shfl_sync(FULL, ce.x, j);
            float u0 = __int_as_float(__shfl_sync(FULL, ce.y, j));
            int s1 = __shfl_sync(FULL, ce.x, j + 1);
            float u1 = __int_as_float(__shfl_sync(FULL, ce.y, j + 1));
            int s2 = __shfl_sync(FULL, ce.x, j + 2);
            float u2 = __int_as_float(__shfl_sync(FULL, ce.y, j + 2));
            int s3 = __shfl_sync(FULL, ce.x, j + 3);
            float u3 = __int_as_float(__shfl_sync(FULL, ce.y, j + 3));
            float2 a0, b0, a1, b1, a2, b2, a3, b3;
            h4_load(src, s0, lane, a0, b0);
            h4_load(src, s1, lane, a1, b1);
            h4_load(src, s2, lane, a2, b2);
            h4_load(src, s3, lane, a3, b3);
            acc.x = fmaf(u0, a0.x, acc.x);  acc2.x = fmaf(u1, a1.x, acc2.x);
            acc.y = fmaf(u0, a0.y, acc.y);  acc2.y = fmaf(u1, a1.y, acc2.y);
            acc.z = fmaf(u0, b0.x, acc.z);  acc2.z = fmaf(u1, b1.x, acc2.z);
            acc.w = fmaf(u0, b0.y, acc.w);  acc2.w = fmaf(u1, b1.y, acc2.w);
            acc.x = fmaf(u2, a2.x, acc.x);  acc2.x = fmaf(u3, a3.x, acc2.x);
            acc.y = fmaf(u2, a2.y, acc.y);  acc2.y = fmaf(u3, a3.y, acc2.y);
            acc.z = fmaf(u2, b2.x, acc.z);  acc2.z = fmaf(u3, b3.x, acc2.z);
            acc.w = fmaf(u2, b2.y, acc.w);  acc2.w = fmaf(u3, b3.y, acc2.w);
        }
        for (; j < take; j++) {
            int s0 = __shfl_sync(FULL, ce.x, j);
            float u0 = __int_as_float(__shfl_sync(FULL, ce.y, j));
            float2 a0, b0;
            h4_load(src, s0, lane, a0, b0);
            acc.x = fmaf(u0, a0.x, acc.x);
            acc.y = fmaf(u0, a0.y, acc.y);
            acc.z = fmaf(u0, b0.x, acc.z);
            acc.w = fmaf(u0, b0.y, acc.w);
        }
        p += take;
    }
    acc.x = (acc.x + acc2.x) * di;
    acc.y = (acc.y + acc2.y) * di;
    acc.z = (acc.z + acc2.z) * di;
    acc.w = (acc.w + acc2.w) * di;
    int f = lane * 4;
    float4 sc4 = *(const float4*)(bnSc + f);
    float4 sh4 = *(const float4*)(bnSh + f);
    acc.x = fmaxf(fmaf(acc.x, sc4.x, sh4.x), 0.f);
    acc.y = fmaxf(fmaf(acc.y, sc4.y, sh4.y), 0.f);
    acc.z = fmaxf(fmaf(acc.z, sc4.z, sh4.z), 0.f);
    acc.w = fmaxf(fmaf(acc.w, sc4.w, sh4.w), 0.f);
    *(float4*)(dst + (size_t)i * H_DIM + lane * 4) = acc;
}

// ====== agg2 (fp16 src) + epi2 fused: s[i] = relu(BN2(agg + res)) . W3 ======
__global__ __launch_bounds__(256) void agg2_epi_kernel(
    const int* __restrict__ rowptr, const int2* __restrict__ csr,
    const __half2* __restrict__ src, const float* __restrict__ res,
    const float* __restrict__ dinv,
    const float* __restrict__ sc2, const float* __restrict__ sh2,
    const float* __restrict__ W3, float* __restrict__ s, int n) {
    int i = (blockIdx.x * blockDim.x + threadIdx.x) >> 5;
    int lane = threadIdx.x & 31;
    if (i >= n) return;
    int p = rowptr[i], pEnd = rowptr[i + 1];
    float di = dinv[i];
    float2 sa, sb;
    h4_load(src, i, lane, sa, sb);
    float4 acc = make_float4(sa.x * di, sa.y * di, sb.x * di, sb.y * di);
    float4 acc2 = make_float4(0.f, 0.f, 0.f, 0.f);
    const unsigned FULL = 0xffffffffu;
    while (p < pEnd) {
        int take = pEnd - p; if (take > 32) take = 32;
        int2 ce = make_int2(0, 0);
        if (lane < take) ce = csr[p + lane];
        int j = 0;
        for (; j + 4 <= take; j += 4) {
            int s0 = __shfl_sync(FULL, ce.x, j);
            float u0 = __int_as_float(__shfl_sync(FULL, ce.y, j));
            int s1 = __shfl_sync(FULL, ce.x, j + 1);
            float u1 = __int_as_float(__shfl_sync(FULL, ce.y, j + 1));
            int s2 = __shfl_sync(FULL, ce.x, j + 2);
            float u2 = __int_as_float(__shfl_sync(FULL, ce.y, j + 2));
            int s3 = __shfl_sync(FULL, ce.x, j + 3);
            float u3 = __int_as_float(__shfl_sync(FULL, ce.y, j + 3));
            float2 a0, b0, a1, b1, a2, b2, a3, b3;
            h4_load(src, s0, lane, a0, b0);
            h4_load(src, s1, lane, a1, b1);
            h4_load(src, s2, lane, a2, b2);
            h4_load(src, s3, lane, a3, b3);
            acc.x = fmaf(u0, a0.x, acc.x);  acc2.x = fmaf(u1, a1.x, acc2.x);
            acc.y = fmaf(u0, a0.y, acc.y);  acc2.y = fmaf(u1, a1.y, acc2.y);
            acc.z = fmaf(u0, b0.x, acc.z);  acc2.z = fmaf(u1, b1.x, acc2.z);
            acc.w = fmaf(u0, b0.y, acc.w);  acc2.w = fmaf(u1, b1.y, acc2.w);
            acc.x = fmaf(u2, a2.x, acc.x);  acc2.x = fmaf(u3, a3.x, acc2.x);
            acc.y = fmaf(u2, a2.y, acc.y);  acc2.y = fmaf(u3, a3.y, acc2.y);
            acc.z = fmaf(u2, b2.x, acc.z);  acc2.z = fmaf(u3, b3.x, acc2.z);
            acc.w = fmaf(u2, b2.y, acc.w);  acc2.w = fmaf(u3, b3.y, acc2.w);
        }
        for (; j < take; j++) {
            int s0 = __shfl_sync(FULL, ce.x, j);
            float u0 = __int_as_float(__shfl_sync(FULL, ce.y, j));
            float2 a0, b0;
            h4_load(src, s0, lane, a0, b0);
            acc.x = fmaf(u0, a0.x, acc.x);
            acc.y = fmaf(u0, a0.y, acc.y);
            acc.z = fmaf(u0, b0.x, acc.z);
            acc.w = fmaf(u0, b0.y, acc.w);
        }
        p += take;
    }
    acc.x += acc2.x; acc.y += acc2.y; acc.z += acc2.z; acc.w += acc2.w;
    int f = lane * 4;
    float4 r4  = *(const float4*)(res + (size_t)i * H_DIM + f);
    float4 sc4 = *(const float4*)(sc2 + f);
    float4 sh4 = *(const float4*)(sh2 + f);
    float4 w4  = *(const float4*)(W3 + f);
    float dot = 0.f;
    dot += fmaxf(fmaf(acc.x * di + r4.x, sc4.x, sh4.x), 0.f) * w4.x;
    dot += fmaxf(fmaf(acc.y * di + r4.y, sc4.y, sh4.y), 0.f) * w4.y;
    dot += fmaxf(fmaf(acc.z * di + r4.z, sc4.z, sh4.z), 0.f) * w4.z;
    dot += fmaxf(fmaf(acc.w * di + r4.w, sc4.w, sh4.w), 0.f) * w4.w;
    #pragma unroll
    for (int off = 16; off; off >>= 1)
        dot += __shfl_down_sync(FULL, dot, off);
    if (lane == 0) s[i] = dot;
}

// ====== layer-3 scalar aggregate ======
__global__ void agg3_kernel(const int* __restrict__ rowptr, const int2* __restrict__ csr,
                            const float* __restrict__ s, const float* __restrict__ dinv,
                            const float* __restrict__ b3, float* __restrict__ out, int n) {
    int i = blockIdx.x * blockDim.x + threadIdx.x;
    if (i >= n) return;
    int p = rowptr[i], pEnd = rowptr[i + 1];
    float di = dinv[i];
    float acc = di * s[i];
    for (; p < pEnd; p++) {
        int2 e = csr[p];
        acc = fmaf(__int_as_float(e.y), s[e.x], acc);
    }
    out[i] = fmaf(di, acc, b3[0]);
}

// ---------------- launch ----------------
extern "C" void kernel_launch(void* const* d_in, const int* in_sizes, int n_in,
                              void* d_out, int out_size) {
    const float* x    = (const float*)d_in[0];
    const int*   ei   = (const int*)d_in[1];     // int32 (jax downcasts int64)
    const float* ew   = (const float*)d_in[2];
    const float* W1   = (const float*)d_in[3];
    const float* b1   = (const float*)d_in[4];
    const float* W2   = (const float*)d_in[5];
    const float* b2   = (const float*)d_in[6];
    const float* W3   = (const float*)d_in[7];
    const float* b3   = (const float*)d_in[8];
    const float* Wres = (const float*)d_in[9];
    const float* g1   = (const float*)d_in[10];
    const float* be1  = (const float*)d_in[11];
    const float* m1   = (const float*)d_in[12];
    const float* v1   = (const float*)d_in[13];
    const float* g2   = (const float*)d_in[14];
    const float* be2  = (const float*)d_in[15];
    const float* m2   = (const float*)d_in[16];
    const float* v2   = (const float*)d_in[17];
    float* out = (float*)d_out;

    int n = in_sizes[0] / V_IN;   // 100000
    int e = in_sizes[2];          // 1600000

    float *deg, *bufR, *bufB, *s, *sc1, *sh1, *sc2, *sh2;
    __half2 *bufE, *bufC;
    int *hist, *rowptr, *cursor, *bsums;
    int2 *csr;
    uint32_t *B1hi, *B1lo, *B2hi, *B2lo;
    cudaGetSymbolAddress((void**)&deg,    g_deg);
    cudaGetSymbolAddress((void**)&hist,   g_hist);
    cudaGetSymbolAddress((void**)&rowptr, g_rowptr);
    cudaGetSymbolAddress((void**)&cursor, g_cursor);
    cudaGetSymbolAddress((void**)&bsums,  g_bsums);
    cudaGetSymbolAddress((void**)&csr,    g_csr);
    cudaGetSymbolAddress((void**)&bufE,   g_bufE);
    cudaGetSymbolAddress((void**)&bufR,   g_bufR);
    cudaGetSymbolAddress((void**)&bufB,   g_bufB);
    cudaGetSymbolAddress((void**)&bufC,   g_bufC);
    cudaGetSymbolAddress((void**)&s,      g_s);
    cudaGetSymbolAddress((void**)&B1hi,   g_B1hi);
    cudaGetSymbolAddress((void**)&B1lo,   g_B1lo);
    cudaGetSymbolAddress((void**)&B2hi,   g_B2hi);
    cudaGetSymbolAddress((void**)&B2lo,   g_B2lo);
    cudaGetSymbolAddress((void**)&sc1,    g_sc1);
    cudaGetSymbolAddress((void**)&sh1,    g_sh1);
    cudaGetSymbolAddress((void**)&sc2,    g_sc2);
    cudaGetSymbolAddress((void**)&sh2,    g_sh2);

    int nb_n   = (n + 255) / 256;
    int nb_e   = (e + 255) / 256;
    int nb_nw  = (n + 7) / 8;                 // warp per node
    int nbScan = (n + 1023) / 1024;           // 98
    int mTiles = (n + 127) / 128;

    // streams/events for graph-parallel branches (host objects; created once)
    static cudaStream_t st1 = nullptr, st2 = nullptr;
    static cudaEvent_t evRoot = nullptr, evCsr = nullptr, evSmall = nullptr;
    if (!st1) {
        cudaStreamCreateWithFlags(&st1, cudaStreamNonBlocking);
        cudaStreamCreateWithFlags(&st2, cudaStreamNonBlocking);
        cudaEventCreateWithFlags(&evRoot,  cudaEventDisableTiming);
        cudaEventCreateWithFlags(&evCsr,   cudaEventDisableTiming);
        cudaEventCreateWithFlags(&evSmall, cudaEventDisableTiming);
    }

    // fork
    cudaEventRecord(evRoot, 0);
    cudaStreamWaitEvent(st1, evRoot, 0);
    cudaStreamWaitEvent(st2, evRoot, 0);

    // branch st1: CSR build chain
    init_kernel<<<nb_n, 256, 0, st1>>>(deg, hist, n);
    deg_hist_kernel<<<nb_e, 256, 0, st1>>>(ei, ew, deg, hist, e);
    deg_fin_kernel<<<nb_n, 256, 0, st1>>>(deg, n);
    scanA_kernel<<<nbScan, 1024, 0, st1>>>(hist, rowptr, bsums, n);
    scanB_kernel<<<1, 128, 0, st1>>>(bsums, nbScan);
    scanC_kernel<<<nbScan, 1024, 0, st1>>>(rowptr, cursor, bsums, n, e);
    fill_kernel<<<nb_e, 256, 0, st1>>>(ei, ew, deg, cursor, csr, e);
    cudaEventRecord(evCsr, st1);

    // branch st2: small weight prep
    split_B2_kernel<<<32, 256, 0, st2>>>(W2, B2hi, B2lo);
    bn_pre_kernel<<<1, 128, 0, st2>>>(b1, g1, be1, m1, v1, b2, g2, be2, m2, v2,
                                      sc1, sh1, sc2, sh2);
    cudaEventRecord(evSmall, st2);

    // main branch: GEMM1 (independent of CSR): bufE(fp16) = x@W1, bufR(fp32) = x@Wres
    split_B1_kernel<<<128, 256>>>(W1, Wres, B1hi, B1lo);
    mma_gemm_kernel<<<dim3(2, mTiles), 256>>>(x, B1hi, B1lo, bufE, bufR, n, 256);

    // join
    cudaStreamWaitEvent(0, evCsr, 0);
    cudaStreamWaitEvent(0, evSmall, 0);

    // agg1 + BN1 + ReLU: bufB = relu(BN1(A_hat @ bufE))
    agg_feat_kernel<<<nb_nw, 256>>>(rowptr, csr, bufE, deg, bufB, sc1, sh1, n);

    // GEMM2: bufC(fp16) = bufB @ W2
    mma_gemm_kernel<<<dim3(1, mTiles), 256>>>(bufB, B2hi, B2lo, bufC, nullptr, n, 128);

    // agg2 + BN2 + res + ReLU + .W3: s
    agg2_epi_kernel<<<nb_nw, 256>>>(rowptr, csr, bufC, bufR, deg, sc2, sh2, W3, s, n);

    // layer 3 scalar aggregate -> out
    agg3_kernel<<<nb_n, 256>>>(rowptr, csr, s, deg, b3, out, n);
}

// round 13
// speedup vs baseline: 4.1102x; 1.2480x over previous
#include <cuda_runtime.h>
#include <cuda_fp16.h>
#include <math.h>
#include <stdint.h>

#define N_NODES 100000
#define E_EDGES 1600000
#define V_IN    256
#define H_DIM   128
#define BN_EPS  1e-5f

// ---------------- scratch (static device globals; no allocs allowed) ----------------
__device__ __align__(16) float g_deg[N_NODES];                 // deg -> dinv (in place)
__device__ __align__(16) int   g_hist[N_NODES];
__device__ __align__(16) int   g_rowptr[N_NODES + 1];
__device__ __align__(16) int   g_cursor[N_NODES];
__device__ __align__(16) int   g_bsums[128];
__device__ __align__(16) int2  g_csr[E_EDGES];                 // {src, bitcast(u=dinv[src]*ew)}
__device__ __align__(16) __half2 g_bufE[(size_t)N_NODES * 64]; // xW1, fp16 pairs
__device__ __align__(16) float g_bufR[(size_t)N_NODES * H_DIM];// x Wres (residual, fp32)
__device__ __align__(16) float g_bufB[(size_t)N_NODES * H_DIM];// h1 = relu(BN1(out1)) fp32
__device__ __align__(16) __half2 g_bufC[(size_t)N_NODES * 64]; // h1@W2, fp16 pairs
__device__ __align__(16) float g_s[N_NODES];                   // h2 @ W3
__device__ __align__(16) uint32_t g_B1[256 * 128];             // [W1|Wres] fp16 pairs [N][K/2]
__device__ __align__(16) uint32_t g_B2[128 * 64];              // W2 fp16 pairs [N][K/2]
__device__ __align__(16) float g_sc1[H_DIM];
__device__ __align__(16) float g_sh1[H_DIM];
__device__ __align__(16) float g_sc2[H_DIM];
__device__ __align__(16) float g_sh2[H_DIM];

// =================== fp16 helpers ===================
__device__ __forceinline__ uint32_t pack_f16x2(float x0, float x1) {
    __half2 h = __floats2half2_rn(x0, x1);      // lo = x0, hi = x1
    return *(uint32_t*)&h;
}
__device__ __forceinline__ void mma_f16(float* d, const uint32_t* a,
                                        uint32_t b0, uint32_t b1) {
    asm volatile(
        "mma.sync.aligned.m16n8k16.row.col.f32.f16.f16.f32 "
        "{%0,%1,%2,%3}, {%4,%5,%6,%7}, {%8,%9}, {%0,%1,%2,%3};"
        : "+f"(d[0]), "+f"(d[1]), "+f"(d[2]), "+f"(d[3])
        : "r"(a[0]), "r"(a[1]), "r"(a[2]), "r"(a[3]), "r"(b0), "r"(b1));
}

// ---------------- degree / histogram ----------------
__global__ void init_kernel(float* deg, int* hist, int n) {
    int i = blockIdx.x * blockDim.x + threadIdx.x;
    if (i < n) { deg[i] = 1.0f; hist[i] = 0; }
}
__global__ void deg_hist_kernel(const int* __restrict__ ei, const float* __restrict__ ew,
                                float* deg, int* hist, int e) {
    int idx = blockIdx.x * blockDim.x + threadIdx.x;
    if (idx < e) {
        int c = ei[e + idx];
        atomicAdd(&deg[c], ew[idx]);
        atomicAdd(&hist[c], 1);
    }
}
__global__ void deg_fin_kernel(float* deg, int n) {
    int i = blockIdx.x * blockDim.x + threadIdx.x;
    if (i < n) deg[i] = rsqrtf(deg[i]);
}

// ---------------- exclusive scan (3 kernels) ----------------
__global__ __launch_bounds__(1024) void scanA_kernel(const int* __restrict__ hist,
                                                     int* __restrict__ excl,
                                                     int* __restrict__ bsums, int n) {
    __shared__ int smw[32];
    int tid = threadIdx.x;
    int gid = blockIdx.x * 1024 + tid;
    int lane = tid & 31, wid = tid >> 5;
    int v = (gid < n) ? hist[gid] : 0;
    int x = v;
    #pragma unroll
    for (int o = 1; o < 32; o <<= 1) {
        int y = __shfl_up_sync(0xffffffffu, x, o);
        if (lane >= o) x += y;
    }
    if (lane == 31) smw[wid] = x;
    __syncthreads();
    if (wid == 0) {
        int s = smw[lane];
        #pragma unroll
        for (int o = 1; o < 32; o <<= 1) {
            int y = __shfl_up_sync(0xffffffffu, s, o);
            if (lane >= o) s += y;
        }
        smw[lane] = s;
    }
    __syncthreads();
    int woff = (wid > 0) ? smw[wid - 1] : 0;
    int incl = x + woff;
    if (gid <= n) excl[gid] = incl - v;
    if (tid == 1023) bsums[blockIdx.x] = incl;
}
__global__ void scanB_kernel(int* bsums, int nb) {
    __shared__ int ws[4];
    int tid = threadIdx.x;
    int lane = tid & 31, wid = tid >> 5;
    int v = (tid < nb) ? bsums[tid] : 0;
    int x = v;
    #pragma unroll
    for (int o = 1; o < 32; o <<= 1) {
        int y = __shfl_up_sync(0xffffffffu, x, o);
        if (lane >= o) x += y;
    }
    if (lane == 31) ws[wid] = x;
    __syncthreads();
    int add = 0;
    #pragma unroll
    for (int w = 0; w < 4; w++) add += (w < wid) ? ws[w] : 0;
    if (tid < nb) bsums[tid] = x + add - v;
}
__global__ void scanC_kernel(int* __restrict__ rowptr, int* __restrict__ cursor,
                             const int* __restrict__ bsums, int n, int e) {
    int gid = blockIdx.x * 1024 + threadIdx.x;
    if (gid < n) {
        int v = rowptr[gid] + bsums[blockIdx.x];
        rowptr[gid] = v;
        cursor[gid] = v;
    }
    if (gid == 0) rowptr[n] = e;
}

// ---------------- CSR fill ----------------
__global__ void fill_kernel(const int* __restrict__ ei, const float* __restrict__ ew,
                            const float* __restrict__ dinv,
                            int* __restrict__ cursor, int2* __restrict__ csr, int e) {
    int idx = blockIdx.x * blockDim.x + threadIdx.x;
    if (idx < e) {
        int r = ei[idx];
        int c = ei[e + idx];
        int pos = atomicAdd(&cursor[c], 1);
        csr[pos] = make_int2(r, __float_as_int(dinv[r] * ew[idx]));
    }
}

// ---------------- weight fp16 pack ----------------
__global__ void pack_B1_kernel(const float* __restrict__ W1, const float* __restrict__ Wres,
                               uint32_t* __restrict__ B) {
    int idx = blockIdx.x * blockDim.x + threadIdx.x;    // 32768; idx = n*128 + p
    int nn = idx >> 7, p = idx & 127;
    float v0, v1;
    if (nn < 128) { v0 = W1[(2 * p) * 128 + nn];          v1 = W1[(2 * p + 1) * 128 + nn]; }
    else          { v0 = Wres[(2 * p) * 128 + nn - 128];  v1 = Wres[(2 * p + 1) * 128 + nn - 128]; }
    B[idx] = pack_f16x2(v0, v1);
}
__global__ void pack_B2_kernel(const float* __restrict__ W2, uint32_t* __restrict__ B) {
    int idx = blockIdx.x * blockDim.x + threadIdx.x;    // 8192; idx = n*64 + p
    int nn = idx >> 6, p = idx & 63;
    B[idx] = pack_f16x2(W2[(2 * p) * 128 + nn], W2[(2 * p + 1) * 128 + nn]);
}
__global__ void bn_pre_kernel(const float* b1, const float* g1, const float* be1,
                              const float* m1, const float* v1,
                              const float* b2, const float* g2, const float* be2,
                              const float* m2, const float* v2,
                              float* sc1, float* sh1, float* sc2, float* sh2) {
    int f = threadIdx.x;
    float s1 = g1[f] * rsqrtf(v1[f] + BN_EPS);
    sc1[f] = s1;
    sh1[f] = (b1[f] - m1[f]) * s1 + be1[f];
    float s2 = g2[f] * rsqrtf(v2[f] + BN_EPS);
    sc2[f] = s2;
    sh2[f] = (b2[f] - m2[f]) * s2 + be2[f];
}

// ====== fp16 MMA GEMM: A[M,K] @ B -> tile n0==0 to half2 Ch, n0==128 to fp32 Cf ======
#define PSTRIDE 20
__global__ __launch_bounds__(256) void mma_gemm_kernel(
    const float* __restrict__ A, const uint32_t* __restrict__ B,
    __half2* __restrict__ Ch, float* __restrict__ Cf, int M, int K) {
    __shared__ uint32_t As[128 * PSTRIDE];
    __shared__ uint32_t Bs[128 * PSTRIDE];

    const int tid = threadIdx.x;
    const int warpId = tid >> 5, lane = tid & 31;
    const int groupID = lane >> 2, tig = lane & 3;
    const int warpM = warpId & 3, warpN = warpId >> 2;
    const int m0 = blockIdx.y * 128;
    const int n0 = blockIdx.x * 128;
    const int Kp = K >> 1;

    float acc[2][8][4];
    #pragma unroll
    for (int i = 0; i < 2; i++)
        #pragma unroll
        for (int j = 0; j < 8; j++)
            #pragma unroll
            for (int q = 0; q < 4; q++) acc[i][j][q] = 0.f;

    const int nChunks = K >> 5;
    for (int c = 0; c < nChunks; c++) {
        #pragma unroll
        for (int t = 0; t < 4; t++) {
            int idx = tid + t * 256;
            int row = idx >> 3;
            int cf = (idx & 7) * 4;
            int gr = m0 + row; if (gr >= M) gr = M - 1;
            float4 v = *(const float4*)(A + (size_t)gr * K + c * 32 + cf);
            uint2 h2;
            h2.x = pack_f16x2(v.x, v.y);
            h2.y = pack_f16x2(v.z, v.w);
            *(uint2*)&As[row * PSTRIDE + (cf >> 1)] = h2;
        }
        #pragma unroll
        for (int t = 0; t < 2; t++) {
            int idx = tid + t * 256;
            int nn = idx >> 2;
            int q = (idx & 3) * 4;
            size_t go = (size_t)(n0 + nn) * Kp + c * 16 + q;
            *(uint4*)&Bs[nn * PSTRIDE + q] = *(const uint4*)(B + go);
        }
        __syncthreads();

        #pragma unroll
        for (int s = 0; s < 2; s++) {
            const int kp = s * 8 + tig;
            uint32_t ah[2][4];
            #pragma unroll
            for (int mt = 0; mt < 2; mt++) {
                int mb = warpM * 32 + mt * 16 + groupID;
                ah[mt][0] = As[mb * PSTRIDE + kp];
                ah[mt][1] = As[(mb + 8) * PSTRIDE + kp];
                ah[mt][2] = As[mb * PSTRIDE + kp + 4];
                ah[mt][3] = As[(mb + 8) * PSTRIDE + kp + 4];
            }
            #pragma unroll
            for (int nt = 0; nt < 8; nt++) {
                int nb = warpN * 64 + nt * 8 + groupID;
                uint32_t b0 = Bs[nb * PSTRIDE + kp];
                uint32_t b1 = Bs[nb * PSTRIDE + kp + 4];
                #pragma unroll
                for (int mt = 0; mt < 2; mt++)
                    mma_f16(acc[mt][nt], ah[mt], b0, b1);
            }
        }
        __syncthreads();
    }

    #pragma unroll
    for (int mt = 0; mt < 2; mt++) {
        int row = m0 + warpM * 32 + mt * 16 + groupID;
        int row2 = row + 8;
        #pragma unroll
        for (int nt = 0; nt < 8; nt++) {
            int col = warpN * 64 + nt * 8 + tig * 2;     // local 0..127
            if (n0 == 0) {
                if (row < M)
                    Ch[(size_t)row * 64 + (col >> 1)] =
                        __floats2half2_rn(acc[mt][nt][0], acc[mt][nt][1]);
                if (row2 < M)
                    Ch[(size_t)row2 * 64 + (col >> 1)] =
                        __floats2half2_rn(acc[mt][nt][2], acc[mt][nt][3]);
            } else {
                if (row < M)
                    *(float2*)(Cf + (size_t)row * H_DIM + col) =
                        make_float2(acc[mt][nt][0], acc[mt][nt][1]);
                if (row2 < M)
                    *(float2*)(Cf + (size_t)row2 * H_DIM + col) =
                        make_float2(acc[mt][nt][2], acc[mt][nt][3]);
            }
        }
    }
}

// ---- fp16 row gather helper: lane covers 4 floats (one uint2 = 2 half2) ----
__device__ __forceinline__ void h4_load(const __half2* __restrict__ base, int row, int lane,
                                        float2& a, float2& b) {
    uint2 raw = *((const uint2*)(base + (size_t)row * 64) + lane);
    a = __half22float2(*(__half2*)&raw.x);
    b = __half22float2(*(__half2*)&raw.y);
}

// ====== agg1 (fp16 src): bufB = relu(BN1(dinv*(sum u*srcRow + dinv*selfRow))) ======
__global__ __launch_bounds__(256) void agg_feat_kernel(
    const int* __restrict__ rowptr, const int2* __restrict__ csr,
    const __half2* __restrict__ src, const float* __restrict__ dinv,
    float* __restrict__ dst,
    const float* __restrict__ bnSc, const float* __restrict__ bnSh, int n) {
    int i = (blockIdx.x * blockDim.x + threadIdx.x) >> 5;
    int lane = threadIdx.x & 31;
    if (i >= n) return;
    int p = rowptr[i], pEnd = rowptr[i + 1];
    float di = dinv[i];
    float2 sa, sb;
    h4_load(src, i, lane, sa, sb);
    float4 acc = make_float4(sa.x * di, sa.y * di, sb.x * di, sb.y * di);
    float4 acc2 = make_float4(0.f, 0.f, 0.f, 0.f);
    const unsigned FULL = 0xffffffffu;
    while (p < pEnd) {
        int take = pEnd - p; if (take > 32) take = 32;
        int2 ce = make_int2(0, 0);
        if (lane < take) ce = csr[p + lane];
        int j = 0;
        for (; j + 4 <= take; j += 4) {
            int s0 = __shfl_sync(FULL, ce.x, j);
            float u0 = __int_as_float(__shfl_sync(FULL, ce.y, j));
            int s1 = __shfl_sync(FULL, ce.x, j + 1);
            float u1 = __int_as_float(__shfl_sync(FULL, ce.y, j + 1));
            int s2 = __shfl_sync(FULL, ce.x, j + 2);
            float u2 = __int_as_float(__shfl_sync(FULL, ce.y, j + 2));
            int s3 = __shfl_sync(FULL, ce.x, j + 3);
            float u3 = __int_as_float(__shfl_sync(FULL, ce.y, j + 3));
            float2 a0, b0, a1, b1, a2, b2, a3, b3;
            h4_load(src, s0, lane, a0, b0);
            h4_load(src, s1, lane, a1, b1);
            h4_load(src, s2, lane, a2, b2);
            h4_load(src, s3, lane, a3, b3);
            acc.x = fmaf(u0, a0.x, acc.x);  acc2.x = fmaf(u1, a1.x, acc2.x);
            acc.y = fmaf(u0, a0.y, acc.y);  acc2.y = fmaf(u1, a1.y, acc2.y);
            acc.z = fmaf(u0, b0.x, acc.z);  acc2.z = fmaf(u1, b1.x, acc2.z);
            acc.w = fmaf(u0, b0.y, acc.w);  acc2.w = fmaf(u1, b1.y, acc2.w);
            acc.x = fmaf(u2, a2.x, acc.x);  acc2.x = fmaf(u3, a3.x, acc2.x);
            acc.y = fmaf(u2, a2.y, acc.y);  acc2.y = fmaf(u3, a3.y, acc2.y);
            acc.z = fmaf(u2, b2.x, acc.z);  acc2.z = fmaf(u3, b3.x, acc2.z);
            acc.w = fmaf(u2, b2.y, acc.w);  acc2.w = fmaf(u3, b3.y, acc2.w);
        }
        for (; j < take; j++) {
            int s0 = __shfl_sync(FULL, ce.x, j);
            float u0 = __int_as_float(__shfl_sync(FULL, ce.y, j));
            float2 a0, b0;
            h4_load(src, s0, lane, a0, b0);
            acc.x = fmaf(u0, a0.x, acc.x);
            acc.y = fmaf(u0, a0.y, acc.y);
            acc.z = fmaf(u0, b0.x, acc.z);
            acc.w = fmaf(u0, b0.y, acc.w);
        }
        p += take;
    }
    acc.x = (acc.x + acc2.x) * di;
    acc.y = (acc.y + acc2.y) * di;
    acc.z = (acc.z + acc2.z) * di;
    acc.w = (acc.w + acc2.w) * di;
    int f = lane * 4;
    float4 sc4 = *(const float4*)(bnSc + f);
    float4 sh4 = *(const float4*)(bnSh + f);
    acc.x = fmaxf(fmaf(acc.x, sc4.x, sh4.x), 0.f);
    acc.y = fmaxf(fmaf(acc.y, sc4.y, sh4.y), 0.f);
    acc.z = fmaxf(fmaf(acc.z, sc4.z, sh4.z), 0.f);
    acc.w = fmaxf(fmaf(acc.w, sc4.w, sh4.w), 0.f);
    *(float4*)(dst + (size_t)i * H_DIM + lane * 4) = acc;
}

// ====== agg2 (fp16 src) + epi2 fused: s[i] = relu(BN2(agg + res)) . W3 ======
__global__ __launch_bounds__(256) void agg2_epi_kernel(
    const int* __restrict__ rowptr, const int2* __restrict__ csr,
    const __half2* __restrict__ src, const float* __restrict__ res,
    const float* __restrict__ dinv,
    const float* __restrict__ sc2, const float* __restrict__ sh2,
    const float* __restrict__ W3, float* __restrict__ s, int n) {
    int i = (blockIdx.x * blockDim.x + threadIdx.x) >> 5;
    int lane = threadIdx.x & 31;
    if (i >= n) return;
    int p = rowptr[i], pEnd = rowptr[i + 1];
    float di = dinv[i];
    float2 sa, sb;
    h4_load(src, i, lane, sa, sb);
    float4 acc = make_float4(sa.x * di, sa.y * di, sb.x * di, sb.y * di);
    float4 acc2 = make_float4(0.f, 0.f, 0.f, 0.f);
    const unsigned FULL = 0xffffffffu;
    while (p < pEnd) {
        int take = pEnd - p; if (take > 32) take = 32;
        int2 ce = make_int2(0, 0);
        if (lane < take) ce = csr[p + lane];
        int j = 0;
        for (; j + 4 <= take; j += 4) {
            int s0 = __shfl_sync(FULL, ce.x, j);
            float u0 = __int_as_float(__shfl_sync(FULL, ce.y, j));
            int s1 = __shfl_sync(FULL, ce.x, j + 1);
            float u1 = __int_as_float(__shfl_sync(FULL, ce.y, j + 1));
            int s2 = __shfl_sync(FULL, ce.x, j + 2);
            float u2 = __int_as_float(__shfl_sync(FULL, ce.y, j + 2));
            int s3 = __shfl_sync(FULL, ce.x, j + 3);
            float u3 = __int_as_float(__shfl_sync(FULL, ce.y, j + 3));
            float2 a0, b0, a1, b1, a2, b2, a3, b3;
            h4_load(src, s0, lane, a0, b0);
            h4_load(src, s1, lane, a1, b1);
            h4_load(src, s2, lane, a2, b2);
            h4_load(src, s3, lane, a3, b3);
            acc.x = fmaf(u0, a0.x, acc.x);  acc2.x = fmaf(u1, a1.x, acc2.x);
            acc.y = fmaf(u0, a0.y, acc.y);  acc2.y = fmaf(u1, a1.y, acc2.y);
            acc.z = fmaf(u0, b0.x, acc.z);  acc2.z = fmaf(u1, b1.x, acc2.z);
            acc.w = fmaf(u0, b0.y, acc.w);  acc2.w = fmaf(u1, b1.y, acc2.w);
            acc.x = fmaf(u2, a2.x, acc.x);  acc2.x = fmaf(u3, a3.x, acc2.x);
            acc.y = fmaf(u2, a2.y, acc.y);  acc2.y = fmaf(u3, a3.y, acc2.y);
            acc.z = fmaf(u2, b2.x, acc.z);  acc2.z = fmaf(u3, b3.x, acc2.z);
            acc.w = fmaf(u2, b2.y, acc.w);  acc2.w = fmaf(u3, b3.y, acc2.w);
        }
        for (; j < take; j++) {
            int s0 = __shfl_sync(FULL, ce.x, j);
            float u0 = __int_as_float(__shfl_sync(FULL, ce.y, j));
            float2 a0, b0;
            h4_load(src, s0, lane, a0, b0);
            acc.x = fmaf(u0, a0.x, acc.x);
            acc.y = fmaf(u0, a0.y, acc.y);
            acc.z = fmaf(u0, b0.x, acc.z);
            acc.w = fmaf(u0, b0.y, acc.w);
        }
        p += take;
    }
    acc.x += acc2.x; acc.y += acc2.y; acc.z += acc2.z; acc.w += acc2.w;
    int f = lane * 4;
    float4 r4  = *(const float4*)(res + (size_t)i * H_DIM + f);
    float4 sc4 = *(const float4*)(sc2 + f);
    float4 sh4 = *(const float4*)(sh2 + f);
    float4 w4  = *(const float4*)(W3 + f);
    float dot = 0.f;
    dot += fmaxf(fmaf(acc.x * di + r4.x, sc4.x, sh4.x), 0.f) * w4.x;
    dot += fmaxf(fmaf(acc.y * di + r4.y, sc4.y, sh4.y), 0.f) * w4.y;
    dot += fmaxf(fmaf(acc.z * di + r4.z, sc4.z, sh4.z), 0.f) * w4.z;
    dot += fmaxf(fmaf(acc.w * di + r4.w, sc4.w, sh4.w), 0.f) * w4.w;
    #pragma unroll
    for (int off = 16; off; off >>= 1)
        dot += __shfl_down_sync(FULL, dot, off);
    if (lane == 0) s[i] = dot;
}

// ====== layer-3 scalar aggregate ======
__global__ void agg3_kernel(const int* __restrict__ rowptr, const int2* __restrict__ csr,
                            const float* __restrict__ s, const float* __restrict__ dinv,
                            const float* __restrict__ b3, float* __restrict__ out, int n) {
    int i = blockIdx.x * blockDim.x + threadIdx.x;
    if (i >= n) return;
    int p = rowptr[i], pEnd = rowptr[i + 1];
    float di = dinv[i];
    float acc = di * s[i];
    for (; p < pEnd; p++) {
        int2 e = csr[p];
        acc = fmaf(__int_as_float(e.y), s[e.x], acc);
    }
    out[i] = fmaf(di, acc, b3[0]);
}

// ---------------- launch ----------------
extern "C" void kernel_launch(void* const* d_in, const int* in_sizes, int n_in,
                              void* d_out, int out_size) {
    const float* x    = (const float*)d_in[0];
    const int*   ei   = (const int*)d_in[1];     // int32 (jax downcasts int64)
    const float* ew   = (const float*)d_in[2];
    const float* W1   = (const float*)d_in[3];
    const float* b1   = (const float*)d_in[4];
    const float* W2   = (const float*)d_in[5];
    const float* b2   = (const float*)d_in[6];
    const float* W3   = (const float*)d_in[7];
    const float* b3   = (const float*)d_in[8];
    const float* Wres = (const float*)d_in[9];
    const float* g1   = (const float*)d_in[10];
    const float* be1  = (const float*)d_in[11];
    const float* m1   = (const float*)d_in[12];
    const float* v1   = (const float*)d_in[13];
    const float* g2   = (const float*)d_in[14];
    const float* be2  = (const float*)d_in[15];
    const float* m2   = (const float*)d_in[16];
    const float* v2   = (const float*)d_in[17];
    float* out = (float*)d_out;

    int n = in_sizes[0] / V_IN;   // 100000
    int e = in_sizes[2];          // 1600000

    float *deg, *bufR, *bufB, *s, *sc1, *sh1, *sc2, *sh2;
    __half2 *bufE, *bufC;
    int *hist, *rowptr, *cursor, *bsums;
    int2 *csr;
    uint32_t *B1, *B2;
    cudaGetSymbolAddress((void**)&deg,    g_deg);
    cudaGetSymbolAddress((void**)&hist,   g_hist);
    cudaGetSymbolAddress((void**)&rowptr, g_rowptr);
    cudaGetSymbolAddress((void**)&cursor, g_cursor);
    cudaGetSymbolAddress((void**)&bsums,  g_bsums);
    cudaGetSymbolAddress((void**)&csr,    g_csr);
    cudaGetSymbolAddress((void**)&bufE,   g_bufE);
    cudaGetSymbolAddress((void**)&bufR,   g_bufR);
    cudaGetSymbolAddress((void**)&bufB,   g_bufB);
    cudaGetSymbolAddress((void**)&bufC,   g_bufC);
    cudaGetSymbolAddress((void**)&s,      g_s);
    cudaGetSymbolAddress((void**)&B1,     g_B1);
    cudaGetSymbolAddress((void**)&B2,     g_B2);
    cudaGetSymbolAddress((void**)&sc1,    g_sc1);
    cudaGetSymbolAddress((void**)&sh1,    g_sh1);
    cudaGetSymbolAddress((void**)&sc2,    g_sc2);
    cudaGetSymbolAddress((void**)&sh2,    g_sh2);

    int nb_n   = (n + 255) / 256;
    int nb_e   = (e + 255) / 256;
    int nb_nw  = (n + 7) / 8;                 // warp per node
    int nbScan = (n + 1023) / 1024;           // 98
    int mTiles = (n + 127) / 128;

    // streams/events for graph-parallel branches (host objects; created once)
    static cudaStream_t st1 = nullptr, st2 = nullptr;
    static cudaEvent_t evRoot = nullptr, evCsr = nullptr, evSmall = nullptr;
    if (!st1) {
        cudaStreamCreateWithFlags(&st1, cudaStreamNonBlocking);
        cudaStreamCreateWithFlags(&st2, cudaStreamNonBlocking);
        cudaEventCreateWithFlags(&evRoot,  cudaEventDisableTiming);
        cudaEventCreateWithFlags(&evCsr,   cudaEventDisableTiming);
        cudaEventCreateWithFlags(&evSmall, cudaEventDisableTiming);
    }

    // fork
    cudaEventRecord(evRoot, 0);
    cudaStreamWaitEvent(st1, evRoot, 0);
    cudaStreamWaitEvent(st2, evRoot, 0);

    // branch st1: CSR build chain
    init_kernel<<<nb_n, 256, 0, st1>>>(deg, hist, n);
    deg_hist_kernel<<<nb_e, 256, 0, st1>>>(ei, ew, deg, hist, e);
    deg_fin_kernel<<<nb_n, 256, 0, st1>>>(deg, n);
    scanA_kernel<<<nbScan, 1024, 0, st1>>>(hist, rowptr, bsums, n);
    scanB_kernel<<<1, 128, 0, st1>>>(bsums, nbScan);
    scanC_kernel<<<nbScan, 1024, 0, st1>>>(rowptr, cursor, bsums, n, e);
    fill_kernel<<<nb_e, 256, 0, st1>>>(ei, ew, deg, cursor, csr, e);
    cudaEventRecord(evCsr, st1);

    // branch st2: small weight prep
    pack_B2_kernel<<<32, 256, 0, st2>>>(W2, B2);
    bn_pre_kernel<<<1, 128, 0, st2>>>(b1, g1, be1, m1, v1, b2, g2, be2, m2, v2,
                                      sc1, sh1, sc2, sh2);
    cudaEventRecord(evSmall, st2);

    // main branch: GEMM1 (independent of CSR): bufE(fp16) = x@W1, bufR(fp32) = x@Wres
    pack_B1_kernel<<<128, 256>>>(W1, Wres, B1);
    mma_gemm_kernel<<<dim3(2, mTiles), 256>>>(x, B1, bufE, bufR, n, 256);

    // join
    cudaStreamWaitEvent(0, evCsr, 0);
    cudaStreamWaitEvent(0, evSmall, 0);

    // agg1 + BN1 + ReLU: bufB = relu(BN1(A_hat @ bufE))
    agg_feat_kernel<<<nb_nw, 256>>>(rowptr, csr, bufE, deg, bufB, sc1, sh1, n);

    // GEMM2: bufC(fp16) = bufB @ W2
    mma_gemm_kernel<<<dim3(1, mTiles), 256>>>(bufB, B2, bufC, nullptr, n, 128);

    // agg2 + BN2 + res + ReLU + .W3: s
    agg2_epi_kernel<<<nb_nw, 256>>>(rowptr, csr, bufC, bufR, deg, sc2, sh2, W3, s, n);

    // layer 3 scalar aggregate -> out
    agg3_kernel<<<nb_n, 256>>>(rowptr, csr, s, deg, b3, out, n);
}